// round 1
// baseline (speedup 1.0000x reference)
#include <cuda_runtime.h>
#include <math.h>

// Problem constants
#define B_   32
#define T_   512
#define H_   256
#define P_   16
#define M_   (B_*T_)     // 16384 rows
#define HP_  4096        // H*P
#define ITERS_ 4

// ---------------- device scratch (static, no allocation) ----------------
__device__ float g_Ett [(size_t)M_*512];    // Et transposed: [B*T, 2H]
__device__ float g_As  [(size_t)M_*HP_];    // Et @ w1s[:, :512]^T + b1s
__device__ float g_Ae  [(size_t)M_*HP_];    // Et @ w1e[:, :512]^T + b1e
__device__ float g_m1  [(size_t)M_*H_];
__device__ float g_m2  [(size_t)M_*H_];
__device__ float g_scores[M_];
__device__ float g_c   [B_*HP_];
__device__ float g_r   [B_*H_];
__device__ float g_encs[B_*512];
__device__ float g_ence[B_*512];
__device__ float g_hx  [B_*H_];
__device__ float g_cx  [B_*H_];

// ---------------- transpose: enc[B,2H,T] -> Ett[B*T, 2H] ----------------
__global__ void transpose_kernel(const float* __restrict__ enc){
  __shared__ float tile[32][33];
  int b  = blockIdx.z;
  int t0 = blockIdx.x*32, c0 = blockIdx.y*32;
  int x  = threadIdx.x;
  for (int i = threadIdx.y; i < 32; i += 8)
    tile[i][x] = enc[((size_t)b*512 + (c0+i))*512 + t0 + x];
  __syncthreads();
  for (int i = threadIdx.y; i < 32; i += 8)
    g_Ett[((size_t)b*512 + (t0+i))*512 + c0 + x] = tile[x][i];
}

// ---------------- init: hx=cx=0, enc_s=enc_e=Et[b,0] ----------------
__global__ void init_kernel(){
  int b = blockIdx.x, t = threadIdx.x;
  float v = g_Ett[((size_t)b*512)*512 + t];
  g_encs[b*512+t] = v;
  g_ence[b*512+t] = v;
  if (t < H_){ g_hx[b*H_+t] = 0.f; g_cx[b*H_+t] = 0.f; }
}

// ---------------- SGEMM: C[M,N] = X[M,K] @ W[N,K]^T (+bias) ----------------
// EPI=0: plain store with bias (ldc = N element stride)
// EPI=1: fused maxout over groups of 16 cols (with bias), C is [M, N/16], ldc=N/16
template<int EPI>
__global__ void __launch_bounds__(256)
sgemm_nt(float* __restrict__ C, int ldc,
         const float* __restrict__ X, int ldx,
         const float* __restrict__ W, int ldw,
         const float* __restrict__ bias,
         int K)
{
  __shared__ float As[8][128];
  __shared__ float Bs[8][128];
  int tid = threadIdx.x;
  int row0 = blockIdx.y*128, col0 = blockIdx.x*128;
  int tx = tid & 15, ty = tid >> 4;
  int lr = tid >> 1;
  int lk = (tid & 1) * 4;
  const float* Xg = X + (size_t)(row0+lr)*ldx + lk;
  const float* Wg = W + (size_t)(col0+lr)*ldw + lk;
  float acc[8][8] = {};
  for (int k0 = 0; k0 < K; k0 += 8){
    float4 xa = *(const float4*)(Xg + k0);
    float4 wa = *(const float4*)(Wg + k0);
    __syncthreads();
    As[lk+0][lr]=xa.x; As[lk+1][lr]=xa.y; As[lk+2][lr]=xa.z; As[lk+3][lr]=xa.w;
    Bs[lk+0][lr]=wa.x; Bs[lk+1][lr]=wa.y; Bs[lk+2][lr]=wa.z; Bs[lk+3][lr]=wa.w;
    __syncthreads();
    #pragma unroll
    for (int k = 0; k < 8; k++){
      float a[8], bb[8];
      *(float4*)(a)    = *(const float4*)&As[k][ty*8];
      *(float4*)(a+4)  = *(const float4*)&As[k][ty*8+4];
      *(float4*)(bb)   = *(const float4*)&Bs[k][tx*8];
      *(float4*)(bb+4) = *(const float4*)&Bs[k][tx*8+4];
      #pragma unroll
      for (int i = 0; i < 8; i++)
        #pragma unroll
        for (int j = 0; j < 8; j++)
          acc[i][j] += a[i]*bb[j];
    }
  }
  float bv[8];
  #pragma unroll
  for (int j = 0; j < 8; j++) bv[j] = bias[col0 + tx*8 + j];
  if (EPI == 0){
    #pragma unroll
    for (int i = 0; i < 8; i++){
      float* cp = C + (size_t)(row0+ty*8+i)*ldc + col0 + tx*8;
      float4 v0 = make_float4(acc[i][0]+bv[0], acc[i][1]+bv[1], acc[i][2]+bv[2], acc[i][3]+bv[3]);
      float4 v1 = make_float4(acc[i][4]+bv[4], acc[i][5]+bv[5], acc[i][6]+bv[6], acc[i][7]+bv[7]);
      *(float4*)cp = v0; *(float4*)(cp+4) = v1;
    }
  } else {
    // maxout over 16 consecutive cols: this thread's 8 + partner lane's 8
    #pragma unroll
    for (int i = 0; i < 8; i++){
      float m = -3.0e38f;
      #pragma unroll
      for (int j = 0; j < 8; j++) m = fmaxf(m, acc[i][j] + bv[j]);
      float o = __shfl_xor_sync(0xffffffffu, m, 1);
      m = fmaxf(m, o);
      if ((tx & 1) == 0)
        C[(size_t)(row0+ty*8+i)*ldc + ((col0 + tx*8) >> 4)] = m;
    }
  }
}

// ---------------- r = tanh([hx|enc_s|enc_e] @ WD^T), WD:[256,1280] ----------------
__global__ void __launch_bounds__(256) r_kernel(const float* __restrict__ WD){
  __shared__ float v[1280];
  int b = blockIdx.x, tid = threadIdx.x;
  v[tid] = g_hx[b*H_+tid];
  for (int i = tid; i < 512; i += 256){
    v[256+i] = g_encs[b*512+i];
    v[768+i] = g_ence[b*512+i];
  }
  __syncthreads();
  const float* w = WD + (size_t)tid*1280;
  float acc = 0.f;
  #pragma unroll 4
  for (int k = 0; k < 1280; k += 4){
    float4 wk = *(const float4*)(w+k);
    acc += wk.x*v[k] + wk.y*v[k+1] + wk.z*v[k+2] + wk.w*v[k+3];
  }
  g_r[b*H_+tid] = tanhf(acc);
}

// ---------------- c[b,j] = r[b,:] . w1[j, 512:768] ----------------
__global__ void __launch_bounds__(256) c_kernel(const float* __restrict__ w1){
  __shared__ float rs[256];
  int b = blockIdx.y, j = blockIdx.x*256 + threadIdx.x;
  rs[threadIdx.x] = g_r[b*H_+threadIdx.x];
  __syncthreads();
  const float* w = w1 + (size_t)j*768 + 512;
  float acc = 0.f;
  #pragma unroll 4
  for (int k = 0; k < 256; k += 4){
    float4 wk = *(const float4*)(w+k);
    acc += wk.x*rs[k] + wk.y*rs[k+1] + wk.z*rs[k+2] + wk.w*rs[k+3];
  }
  g_c[b*HP_+j] = acc;
}

// ---------------- m1[row,h] = max_p (A[row, h*16+p] + c[b, h*16+p]) ----------------
__global__ void __launch_bounds__(256) m1_kernel(const float* __restrict__ A){
  int row = blockIdx.x, h = threadIdx.x, b = row >> 9;
  const float4* ap = (const float4*)(A   + (size_t)row*HP_ + h*16);
  const float4* cp = (const float4*)(g_c + (size_t)b  *HP_ + h*16);
  float m = -3.0e38f;
  #pragma unroll
  for (int q = 0; q < 4; q++){
    float4 a = ap[q], c = cp[q];
    m = fmaxf(m, fmaxf(fmaxf(a.x+c.x, a.y+c.y), fmaxf(a.z+c.z, a.w+c.w)));
  }
  g_m1[(size_t)row*H_ + h] = m;
}

// ---------------- scores[row] = max_p ([m1|m2] . w3[p,:] + b3[p]) ----------------
__global__ void __launch_bounds__(256) score_kernel(const float* __restrict__ w3,
                                                   const float* __restrict__ b3){
  __shared__ float ws[16][512];
  int tid = threadIdx.x;
  for (int i = tid; i < 16*512; i += 256) ((float*)ws)[i] = w3[i];
  __syncthreads();
  int warp = tid >> 5, lane = tid & 31;
  size_t row = (size_t)blockIdx.x*8 + warp;
  const float* m1r = g_m1 + row*H_;
  const float* m2r = g_m2 + row*H_;
  float acc[16];
  #pragma unroll
  for (int p = 0; p < 16; p++) acc[p] = 0.f;
  #pragma unroll
  for (int kk = 0; kk < 512; kk += 128){
    int k = kk + lane*4;
    float4 x = (k < 256) ? *(const float4*)(m1r + k) : *(const float4*)(m2r + k - 256);
    #pragma unroll
    for (int p = 0; p < 16; p++){
      float4 wv = *(const float4*)&ws[p][k];
      acc[p] += x.x*wv.x + x.y*wv.y + x.z*wv.z + x.w*wv.w;
    }
  }
  #pragma unroll
  for (int p = 0; p < 16; p++)
    #pragma unroll
    for (int off = 16; off; off >>= 1)
      acc[p] += __shfl_xor_sync(0xffffffffu, acc[p], off);
  if (lane == 0){
    float m = -3.0e38f;
    #pragma unroll
    for (int p = 0; p < 16; p++) m = fmaxf(m, acc[p] + b3[p]);
    g_scores[row] = m;
  }
}

// ---------------- masked argmax (first-index), write alphas + idx + gather enc ----------------
__global__ void __launch_bounds__(512) argmax_kernel(const int* __restrict__ lens,
    float* __restrict__ alphas, float* __restrict__ idx_out, float* __restrict__ enc)
{
  __shared__ float sv[512];
  __shared__ int   si[512];
  int b = blockIdx.x, t = threadIdx.x;
  float s = g_scores[b*T_+t] - ((t < lens[b]) ? 0.f : 1.0e9f);
  alphas[(size_t)b*T_ + t] = s;
  sv[t] = s; si[t] = t;
  __syncthreads();
  for (int off = 256; off; off >>= 1){
    if (t < off){
      float v2 = sv[t+off]; int i2 = si[t+off];
      if (v2 > sv[t] || (v2 == sv[t] && i2 < si[t])) { sv[t] = v2; si[t] = i2; }
    }
    __syncthreads();
  }
  int idx = si[0];
  enc[b*512 + t] = g_Ett[((size_t)b*T_ + idx)*512 + t];
  if (t == 0) idx_out[b] = (float)idx;
}

// ---------------- LSTM cell + MLP ----------------
__global__ void __launch_bounds__(1024) lstm_kernel(
  const float* __restrict__ Wih, const float* __restrict__ Whh,
  const float* __restrict__ bih, const float* __restrict__ bhh,
  const float* __restrict__ Wmlp, const float* __restrict__ bmlp)
{
  __shared__ float xs[1024];
  __shared__ float hs[256];
  __shared__ float gsh[1024];
  __shared__ float hp[256];
  int b = blockIdx.x, tid = threadIdx.x;
  if (tid < 512) xs[tid] = g_encs[b*512+tid];
  else           xs[tid] = g_ence[b*512+tid-512];
  if (tid < 256) hs[tid] = g_hx[b*256+tid];
  __syncthreads();
  {
    const float* wi = Wih + (size_t)tid*1024;
    float acc = bih[tid] + bhh[tid];
    #pragma unroll 4
    for (int k = 0; k < 1024; k += 4){
      float4 w = *(const float4*)(wi+k);
      acc += w.x*xs[k] + w.y*xs[k+1] + w.z*xs[k+2] + w.w*xs[k+3];
    }
    const float* wh = Whh + (size_t)tid*256;
    #pragma unroll 4
    for (int k = 0; k < 256; k += 4){
      float4 w = *(const float4*)(wh+k);
      acc += w.x*hs[k] + w.y*hs[k+1] + w.z*hs[k+2] + w.w*hs[k+3];
    }
    gsh[tid] = acc;
  }
  __syncthreads();
  if (tid < 256){
    float i_ = 1.f/(1.f+expf(-gsh[tid]));
    float f_ = 1.f/(1.f+expf(-gsh[256+tid]));
    float gg = tanhf(gsh[512+tid]);
    float o_ = 1.f/(1.f+expf(-gsh[768+tid]));
    float c  = f_*g_cx[b*256+tid] + i_*gg;
    g_cx[b*256+tid] = c;
    hp[tid] = o_*tanhf(c);
  }
  __syncthreads();
  if (tid < 256){
    const float* wm = Wmlp + (size_t)tid*256;
    float acc = bmlp[tid];
    #pragma unroll 4
    for (int k = 0; k < 256; k += 4){
      float4 w = *(const float4*)(wm+k);
      acc += w.x*hp[k] + w.y*hp[k+1] + w.z*hp[k+2] + w.w*hp[k+3];
    }
    g_hx[b*256+tid] = acc;
  }
}

// ---------------- host orchestration ----------------
extern "C" void kernel_launch(void* const* d_in, const int* in_sizes, int n_in,
                              void* d_out, int out_size)
{
  (void)in_sizes; (void)n_in; (void)out_size;
  const float* enc =(const float*)d_in[0];
  const int*   lens=(const int*)  d_in[1];
  const float* WDs =(const float*)d_in[2];
  const float* w1s =(const float*)d_in[3];  const float* b1s=(const float*)d_in[4];
  const float* w2s =(const float*)d_in[5];  const float* b2s=(const float*)d_in[6];
  const float* w3s =(const float*)d_in[7];  const float* b3s=(const float*)d_in[8];
  const float* WDe =(const float*)d_in[9];
  const float* w1e =(const float*)d_in[10]; const float* b1e=(const float*)d_in[11];
  const float* w2e =(const float*)d_in[12]; const float* b2e=(const float*)d_in[13];
  const float* w3e =(const float*)d_in[14]; const float* b3e=(const float*)d_in[15];
  const float* Wih =(const float*)d_in[16]; const float* Whh=(const float*)d_in[17];
  const float* bih =(const float*)d_in[18]; const float* bhh=(const float*)d_in[19];
  const float* Wmlp=(const float*)d_in[20]; const float* bmlp=(const float*)d_in[21];

  float* out = (float*)d_out;
  float* out_start  = out;
  float* out_end    = out + 32;
  float* out_alphas = out + 64;
  float* out_betas  = out + 64 + (size_t)ITERS_*B_*T_;

  float *pAs,*pAe,*pm1,*pm2,*pencs,*pence,*pEtt;
  cudaGetSymbolAddress((void**)&pAs,  g_As);
  cudaGetSymbolAddress((void**)&pAe,  g_Ae);
  cudaGetSymbolAddress((void**)&pm1,  g_m1);
  cudaGetSymbolAddress((void**)&pm2,  g_m2);
  cudaGetSymbolAddress((void**)&pencs,g_encs);
  cudaGetSymbolAddress((void**)&pence,g_ence);
  cudaGetSymbolAddress((void**)&pEtt, g_Ett);

  transpose_kernel<<<dim3(16,16,32), dim3(32,8)>>>(enc);
  init_kernel<<<32,512>>>();

  dim3 gBig(HP_/128, M_/128);   // (32, 128)
  // Iteration-independent precompute: A = Et @ w1[:, :512]^T + b1
  sgemm_nt<0><<<gBig,256>>>(pAs, HP_, pEtt, 512, w1s, 768, b1s, 512);
  sgemm_nt<0><<<gBig,256>>>(pAe, HP_, pEtt, 512, w1e, 768, b1e, 512);

  for (int it = 0; it < ITERS_; ++it){
    // ---- start net ----
    r_kernel<<<32,256>>>(WDs);
    c_kernel<<<dim3(16,32),256>>>(w1s);
    m1_kernel<<<M_,256>>>(pAs);
    sgemm_nt<1><<<gBig,256>>>(pm2, 256, pm1, 256, w2s, 256, b2s, 256);
    score_kernel<<<M_/8,256>>>(w3s, b3s);
    argmax_kernel<<<32,512>>>(lens, out_alphas + (size_t)it*B_*T_, out_start, pencs);
    // ---- end net ----
    r_kernel<<<32,256>>>(WDe);
    c_kernel<<<dim3(16,32),256>>>(w1e);
    m1_kernel<<<M_,256>>>(pAe);
    sgemm_nt<1><<<gBig,256>>>(pm2, 256, pm1, 256, w2e, 256, b2e, 256);
    score_kernel<<<M_/8,256>>>(w3e, b3e);
    argmax_kernel<<<32,512>>>(lens, out_betas + (size_t)it*B_*T_, out_end, pence);
    // ---- LSTM + MLP state update ----
    lstm_kernel<<<32,1024>>>(Wih, Whh, bih, bhh, Wmlp, bmlp);
  }
}

// round 3
// speedup vs baseline: 1.9724x; 1.9724x over previous
#include <cuda_runtime.h>
#include <cuda_fp16.h>
#include <math.h>
#include <stdint.h>

// Problem constants
#define B_   32
#define T_   512
#define H_   256
#define P_   16
#define M_   (B_*T_)     // 16384 rows
#define HP_  4096        // H*P
#define ITERS_ 4

// ================= device scratch (static, no allocation) =================
__device__ float g_Ett [(size_t)M_*512];
__device__ float g_As  [(size_t)M_*HP_];
__device__ float g_Ae  [(size_t)M_*HP_];
__device__ float g_m1  [(size_t)M_*H_];
__device__ float g_m2  [(size_t)M_*H_];
__device__ float g_scores[M_];
__device__ float g_c   [B_*HP_];
__device__ float g_r   [B_*H_];
__device__ float g_encs[B_*512];
__device__ float g_ence[B_*512];
__device__ float g_hx  [B_*H_];
__device__ float g_cx  [B_*H_];

// fp16 split arrays (h/m)
__device__ __half g_EttS [2][(size_t)M_*512];
__device__ __half g_w1sS [2][(size_t)HP_*512];
__device__ __half g_w1eS [2][(size_t)HP_*512];
__device__ __half g_w2sS [2][(size_t)HP_*256];
__device__ __half g_w2eS [2][(size_t)HP_*256];
__device__ __half g_m1S  [2][(size_t)M_*256];

// ================= helpers =================
__device__ __forceinline__ uint32_t smem_u32(const void* p){
  uint32_t a;
  asm("{ .reg .u64 t; cvta.to.shared.u64 t, %1; cvt.u32.u64 %0, t; }" : "=r"(a) : "l"(p));
  return a;
}
__device__ __forceinline__ void cpa16(uint32_t dst, const void* src){
  asm volatile("cp.async.ca.shared.global [%0], [%1], 16;" :: "r"(dst), "l"(src));
}
#define CP_COMMIT() asm volatile("cp.async.commit_group;" ::: "memory")
#define CP_WAIT2()  asm volatile("cp.async.wait_group 2;"  ::: "memory")

#define LDSM4(r, a) \
  asm volatile("ldmatrix.sync.aligned.m8n8.x4.shared.b16 {%0,%1,%2,%3}, [%4];" \
    : "=r"((r)[0]),"=r"((r)[1]),"=r"((r)[2]),"=r"((r)[3]) : "r"(a))

#define MMA16816(d, a, b0, b1) \
  asm volatile("mma.sync.aligned.m16n8k16.row.col.f32.f16.f16.f32 " \
    "{%0,%1,%2,%3}, {%4,%5,%6,%7}, {%8,%9}, {%0,%1,%2,%3};" \
    : "+f"((d)[0]),"+f"((d)[1]),"+f"((d)[2]),"+f"((d)[3]) \
    : "r"((a)[0]),"r"((a)[1]),"r"((a)[2]),"r"((a)[3]), "r"(b0),"r"(b1))

// ================= transpose: enc[B,2H,T] -> Ett[B*T, 2H] =================
__global__ void transpose_kernel(const float* __restrict__ enc){
  __shared__ float tile[32][33];
  int b  = blockIdx.z;
  int t0 = blockIdx.x*32, c0 = blockIdx.y*32;
  int x  = threadIdx.x;
  for (int i = threadIdx.y; i < 32; i += 8)
    tile[i][x] = enc[((size_t)b*512 + (c0+i))*512 + t0 + x];
  __syncthreads();
  for (int i = threadIdx.y; i < 32; i += 8)
    g_Ett[((size_t)b*512 + (t0+i))*512 + c0 + x] = tile[x][i];
}

__global__ void init_kernel(){
  int b = blockIdx.x, t = threadIdx.x;
  float v = g_Ett[((size_t)b*512)*512 + t];
  g_encs[b*512+t] = v;
  g_ence[b*512+t] = v;
  if (t < H_){ g_hx[b*H_+t] = 0.f; g_cx[b*H_+t] = 0.f; }
}

// ================= fp32 -> 2x fp16 split =================
__global__ void __launch_bounds__(256) split2_kernel(const float* __restrict__ src, int ld, int cols,
    __half* __restrict__ oh, __half* __restrict__ om, int total)
{
  int idx = blockIdx.x*256 + threadIdx.x;
  if (idx >= total) return;
  int r = idx / cols, c = idx - r*cols;
  float x = src[(size_t)r*ld + c];
  __half h = __float2half_rn(x);
  oh[idx] = h;
  om[idx] = __float2half_rn(x - __half2float(h));
}

// ================= HMMA split-3 GEMM: C[M,N] = X[M,K] @ W[N,K]^T =================
// CTA tile 256x128, 8 warps (4x2), warp tile 64x64. K-chunks of 16.
// Per chunk loads Ah,Am,Bh,Bm; runs 3 passes (hh, mh, hm) into fp32 acc.
// EPI=0: bias + fp32 store (ldc). EPI=1: bias + maxout over 16-col groups (ldc = N/16).
#define STAGE_BYTES 24576   // Ah 8K | Am 8K | Bh 4K | Bm 4K
#define NSTG 4
#define GEMM_SMEM (NSTG*STAGE_BYTES)

template<int EPI>
__global__ void __launch_bounds__(256, 1)
hgemm(float* __restrict__ C, int ldc,
      const __half* __restrict__ Ah, const __half* __restrict__ Am,
      const __half* __restrict__ Bh, const __half* __restrict__ Bm,
      const float* __restrict__ bias, int K)
{
  extern __shared__ char smem[];
  uint32_t sb = smem_u32(smem);
  const int tid = threadIdx.x, lane = tid & 31, warp = tid >> 5;
  const int wm = warp >> 1, wn = warp & 1;
  const int row0 = blockIdx.y*256, col0 = blockIdx.x*128;
  const int nsteps = K >> 4;

  // per-thread cp.async source pointers / smem dest offsets
  const __half* gAh = Ah + (size_t)(row0 + tid)*K;
  const __half* gAm = Am + (size_t)(row0 + tid)*K;
  const __half* gBh = Bh + (size_t)(col0 + (tid>>1))*K + (tid&1)*8;
  const __half* gBm = Bm + (size_t)(col0 + (tid>>1))*K + (tid&1)*8;
  const uint32_t swa = (tid>>2)&1;
  const uint32_t dA0 = 16*(tid*2 + swa);
  const uint32_t dA1 = 16*(tid*2 + (1u^swa));
  const uint32_t dB  = 16*((tid>>1)*2 + ((tid&1) ^ ((tid>>3)&1)));

  auto issue = [&](int s){
    uint32_t st = sb + (uint32_t)(s & (NSTG-1))*STAGE_BYTES;
    const __half* a0 = gAh + s*16;
    const __half* a1 = gAm + s*16;
    cpa16(st+dA0, a0);            cpa16(st+dA1, a0+8);
    cpa16(st+8192+dA0, a1);       cpa16(st+8192+dA1, a1+8);
    cpa16(st+16384+dB, gBh + s*16);
    cpa16(st+20480+dB, gBm + s*16);
  };

  // ldmatrix per-lane offsets (stage-relative)
  uint32_t aoff[4], boff[4];
  #pragma unroll
  for (int mi = 0; mi < 4; mi++){
    int r = wm*64 + mi*16 + (lane & 15);
    int c = lane >> 4;
    aoff[mi] = 16*(r*2 + (c ^ ((r>>2)&1)));
  }
  #pragma unroll
  for (int nj = 0; nj < 4; nj++){
    int n = wn*64 + nj*16 + (lane & 7) + ((lane>>4)<<3);
    int c = (lane>>3)&1;
    boff[nj] = 16384 + 16*(n*2 + (c ^ ((n>>2)&1)));
  }

  float acc[4][8][4];
  #pragma unroll
  for (int mi = 0; mi < 4; mi++)
    #pragma unroll
    for (int q = 0; q < 8; q++)
      #pragma unroll
      for (int v = 0; v < 4; v++) acc[mi][q][v] = 0.f;

  issue(0); CP_COMMIT();
  issue(1); CP_COMMIT();
  issue(2); CP_COMMIT();

  for (int i = 0; i < nsteps; i++){
    CP_WAIT2();
    __syncthreads();
    if (i+3 < nsteps) issue(i+3);
    CP_COMMIT();
    uint32_t st = sb + (uint32_t)(i & (NSTG-1))*STAGE_BYTES;

    uint32_t ah[4][4], am[4][4], bh[4][4], bm[4][4];
    #pragma unroll
    for (int mi = 0; mi < 4; mi++){
      LDSM4(ah[mi], st + aoff[mi]);
      LDSM4(am[mi], st + 8192 + aoff[mi]);
    }
    #pragma unroll
    for (int nj = 0; nj < 4; nj++){
      LDSM4(bh[nj], st + boff[nj]);
      LDSM4(bm[nj], st + 4096 + boff[nj]);
    }
    #pragma unroll
    for (int mi = 0; mi < 4; mi++){
      #pragma unroll
      for (int q = 0; q < 8; q++){
        uint32_t b0 = bh[q>>1][(q&1)*2], b1 = bh[q>>1][(q&1)*2+1];
        MMA16816(acc[mi][q], ah[mi], b0, b1);   // hh
        MMA16816(acc[mi][q], am[mi], b0, b1);   // mh
        uint32_t c0 = bm[q>>1][(q&1)*2], c1 = bm[q>>1][(q&1)*2+1];
        MMA16816(acc[mi][q], ah[mi], c0, c1);   // hm
      }
    }
  }

  // epilogue
  #pragma unroll
  for (int mi = 0; mi < 4; mi++){
    int r0 = row0 + wm*64 + mi*16 + (lane>>2);
    int r1 = r0 + 8;
    if (EPI == 0){
      #pragma unroll
      for (int q = 0; q < 8; q++){
        int cb = col0 + wn*64 + q*8 + 2*(lane&3);
        float bv0 = __ldg(bias+cb), bv1 = __ldg(bias+cb+1);
        *(float2*)(C + (size_t)r0*ldc + cb) = make_float2(acc[mi][q][0]+bv0, acc[mi][q][1]+bv1);
        *(float2*)(C + (size_t)r1*ldc + cb) = make_float2(acc[mi][q][2]+bv0, acc[mi][q][3]+bv1);
      }
    } else {
      #pragma unroll
      for (int g = 0; g < 4; g++){
        int cb = col0 + wn*64 + g*16;
        int cA = cb + 2*(lane&3), cB = cb + 8 + 2*(lane&3);
        float bA0 = __ldg(bias+cA), bA1 = __ldg(bias+cA+1);
        float bB0 = __ldg(bias+cB), bB1 = __ldg(bias+cB+1);
        float v0 = fmaxf(fmaxf(acc[mi][2*g][0]+bA0, acc[mi][2*g][1]+bA1),
                         fmaxf(acc[mi][2*g+1][0]+bB0, acc[mi][2*g+1][1]+bB1));
        float v1 = fmaxf(fmaxf(acc[mi][2*g][2]+bA0, acc[mi][2*g][3]+bA1),
                         fmaxf(acc[mi][2*g+1][2]+bB0, acc[mi][2*g+1][3]+bB1));
        v0 = fmaxf(v0, __shfl_xor_sync(0xffffffffu, v0, 1));
        v0 = fmaxf(v0, __shfl_xor_sync(0xffffffffu, v0, 2));
        v1 = fmaxf(v1, __shfl_xor_sync(0xffffffffu, v1, 1));
        v1 = fmaxf(v1, __shfl_xor_sync(0xffffffffu, v1, 2));
        if ((lane & 3) == 0){
          C[(size_t)r0*ldc + (cb>>4)] = v0;
          C[(size_t)r1*ldc + (cb>>4)] = v1;
        }
      }
    }
  }
}

// ================= r = tanh([hx|enc_s|enc_e] @ WD^T) =================
__global__ void __launch_bounds__(256) r_kernel(const float* __restrict__ WD){
  __shared__ float v[1280];
  int b = blockIdx.x, tid = threadIdx.x;
  v[tid] = g_hx[b*H_+tid];
  for (int i = tid; i < 512; i += 256){
    v[256+i] = g_encs[b*512+i];
    v[768+i] = g_ence[b*512+i];
  }
  __syncthreads();
  const float* w = WD + (size_t)tid*1280;
  float acc = 0.f;
  #pragma unroll 4
  for (int k = 0; k < 1280; k += 4){
    float4 wk = *(const float4*)(w+k);
    acc += wk.x*v[k] + wk.y*v[k+1] + wk.z*v[k+2] + wk.w*v[k+3];
  }
  g_r[b*H_+tid] = tanhf(acc);
}

// ================= c[b,j] = r[b,:] . w1[j, 512:768] =================
__global__ void __launch_bounds__(256) c_kernel(const float* __restrict__ w1){
  __shared__ float rs[256];
  int b = blockIdx.y, j = blockIdx.x*256 + threadIdx.x;
  rs[threadIdx.x] = g_r[b*H_+threadIdx.x];
  __syncthreads();
  const float* w = w1 + (size_t)j*768 + 512;
  float acc = 0.f;
  #pragma unroll 4
  for (int k = 0; k < 256; k += 4){
    float4 wk = *(const float4*)(w+k);
    acc += wk.x*rs[k] + wk.y*rs[k+1] + wk.z*rs[k+2] + wk.w*rs[k+3];
  }
  g_c[b*HP_+j] = acc;
}

// ====== m1[row,h] = max_p(A[row,h*16+p] + c[b,h*16+p]); emit fp16 splits ======
__global__ void __launch_bounds__(256) m1_kernel(const float* __restrict__ A){
  int row = blockIdx.x, h = threadIdx.x, b = row >> 9;
  const float4* ap = (const float4*)(A   + (size_t)row*HP_ + h*16);
  const float4* cp = (const float4*)(g_c + (size_t)b  *HP_ + h*16);
  float m = -3.0e38f;
  #pragma unroll
  for (int q = 0; q < 4; q++){
    float4 a = ap[q], c = cp[q];
    m = fmaxf(m, fmaxf(fmaxf(a.x+c.x, a.y+c.y), fmaxf(a.z+c.z, a.w+c.w)));
  }
  size_t o = (size_t)row*H_ + h;
  g_m1[o] = m;
  __half hh = __float2half_rn(m);
  g_m1S[0][o] = hh;
  g_m1S[1][o] = __float2half_rn(m - __half2float(hh));
}

// ================= scores[row] = max_p([m1|m2] . w3[p,:] + b3[p]) =================
__global__ void __launch_bounds__(256) score_kernel(const float* __restrict__ w3,
                                                   const float* __restrict__ b3){
  __shared__ float ws[16][512];
  int tid = threadIdx.x;
  for (int i = tid; i < 16*512; i += 256) ((float*)ws)[i] = w3[i];
  __syncthreads();
  int warp = tid >> 5, lane = tid & 31;
  size_t row = (size_t)blockIdx.x*8 + warp;
  const float* m1r = g_m1 + row*H_;
  const float* m2r = g_m2 + row*H_;
  float acc[16];
  #pragma unroll
  for (int p = 0; p < 16; p++) acc[p] = 0.f;
  #pragma unroll
  for (int kk = 0; kk < 512; kk += 128){
    int k = kk + lane*4;
    float4 x = (k < 256) ? *(const float4*)(m1r + k) : *(const float4*)(m2r + k - 256);
    #pragma unroll
    for (int p = 0; p < 16; p++){
      float4 wv = *(const float4*)&ws[p][k];
      acc[p] += x.x*wv.x + x.y*wv.y + x.z*wv.z + x.w*wv.w;
    }
  }
  #pragma unroll
  for (int p = 0; p < 16; p++)
    #pragma unroll
    for (int off = 16; off; off >>= 1)
      acc[p] += __shfl_xor_sync(0xffffffffu, acc[p], off);
  if (lane == 0){
    float m = -3.0e38f;
    #pragma unroll
    for (int p = 0; p < 16; p++) m = fmaxf(m, acc[p] + b3[p]);
    g_scores[row] = m;
  }
}

// ================= masked argmax + gather =================
__global__ void __launch_bounds__(512) argmax_kernel(const int* __restrict__ lens,
    float* __restrict__ alphas, float* __restrict__ idx_out, float* __restrict__ enc)
{
  __shared__ float sv[512];
  __shared__ int   si[512];
  int b = blockIdx.x, t = threadIdx.x;
  float s = g_scores[b*T_+t] - ((t < lens[b]) ? 0.f : 1.0e9f);
  alphas[(size_t)b*T_ + t] = s;
  sv[t] = s; si[t] = t;
  __syncthreads();
  for (int off = 256; off; off >>= 1){
    if (t < off){
      float v2 = sv[t+off]; int i2 = si[t+off];
      if (v2 > sv[t] || (v2 == sv[t] && i2 < si[t])) { sv[t] = v2; si[t] = i2; }
    }
    __syncthreads();
  }
  int idx = si[0];
  enc[b*512 + t] = g_Ett[((size_t)b*T_ + idx)*512 + t];
  if (t == 0) idx_out[b] = (float)idx;
}

// ================= LSTM cell + MLP =================
__global__ void __launch_bounds__(1024) lstm_kernel(
  const float* __restrict__ Wih, const float* __restrict__ Whh,
  const float* __restrict__ bih, const float* __restrict__ bhh,
  const float* __restrict__ Wmlp, const float* __restrict__ bmlp)
{
  __shared__ float xs[1024];
  __shared__ float hs[256];
  __shared__ float gsh[1024];
  __shared__ float hp[256];
  int b = blockIdx.x, tid = threadIdx.x;
  if (tid < 512) xs[tid] = g_encs[b*512+tid];
  else           xs[tid] = g_ence[b*512+tid-512];
  if (tid < 256) hs[tid] = g_hx[b*256+tid];
  __syncthreads();
  {
    const float* wi = Wih + (size_t)tid*1024;
    float acc = bih[tid] + bhh[tid];
    #pragma unroll 4
    for (int k = 0; k < 1024; k += 4){
      float4 w = *(const float4*)(wi+k);
      acc += w.x*xs[k] + w.y*xs[k+1] + w.z*xs[k+2] + w.w*xs[k+3];
    }
    const float* wh = Whh + (size_t)tid*256;
    #pragma unroll 4
    for (int k = 0; k < 256; k += 4){
      float4 w = *(const float4*)(wh+k);
      acc += w.x*hs[k] + w.y*hs[k+1] + w.z*hs[k+2] + w.w*hs[k+3];
    }
    gsh[tid] = acc;
  }
  __syncthreads();
  if (tid < 256){
    float i_ = 1.f/(1.f+expf(-gsh[tid]));
    float f_ = 1.f/(1.f+expf(-gsh[256+tid]));
    float gg = tanhf(gsh[512+tid]);
    float o_ = 1.f/(1.f+expf(-gsh[768+tid]));
    float c  = f_*g_cx[b*256+tid] + i_*gg;
    g_cx[b*256+tid] = c;
    hp[tid] = o_*tanhf(c);
  }
  __syncthreads();
  if (tid < 256){
    const float* wm = Wmlp + (size_t)tid*256;
    float acc = bmlp[tid];
    #pragma unroll 4
    for (int k = 0; k < 256; k += 4){
      float4 w = *(const float4*)(wm+k);
      acc += w.x*hp[k] + w.y*hp[k+1] + w.z*hp[k+2] + w.w*hp[k+3];
    }
    g_hx[b*256+tid] = acc;
  }
}

// ================= host orchestration =================
extern "C" void kernel_launch(void* const* d_in, const int* in_sizes, int n_in,
                              void* d_out, int out_size)
{
  (void)in_sizes; (void)n_in; (void)out_size;
  const float* enc =(const float*)d_in[0];
  const int*   lens=(const int*)  d_in[1];
  const float* WDs =(const float*)d_in[2];
  const float* w1s =(const float*)d_in[3];  const float* b1s=(const float*)d_in[4];
  const float* w2s =(const float*)d_in[5];  const float* b2s=(const float*)d_in[6];
  const float* w3s =(const float*)d_in[7];  const float* b3s=(const float*)d_in[8];
  const float* WDe =(const float*)d_in[9];
  const float* w1e =(const float*)d_in[10]; const float* b1e=(const float*)d_in[11];
  const float* w2e =(const float*)d_in[12]; const float* b2e=(const float*)d_in[13];
  const float* w3e =(const float*)d_in[14]; const float* b3e=(const float*)d_in[15];
  const float* Wih =(const float*)d_in[16]; const float* Whh=(const float*)d_in[17];
  const float* bih =(const float*)d_in[18]; const float* bhh=(const float*)d_in[19];
  const float* Wmlp=(const float*)d_in[20]; const float* bmlp=(const float*)d_in[21];

  float* out = (float*)d_out;
  float* out_start  = out;
  float* out_end    = out + 32;
  float* out_alphas = out + 64;
  float* out_betas  = out + 64 + (size_t)ITERS_*B_*T_;

  float *pAs,*pAe,*pm1,*pm2,*pencs,*pence,*pEtt;
  cudaGetSymbolAddress((void**)&pAs,  g_As);
  cudaGetSymbolAddress((void**)&pAe,  g_Ae);
  cudaGetSymbolAddress((void**)&pm1,  g_m1);
  cudaGetSymbolAddress((void**)&pm2,  g_m2);
  cudaGetSymbolAddress((void**)&pencs,g_encs);
  cudaGetSymbolAddress((void**)&pence,g_ence);
  cudaGetSymbolAddress((void**)&pEtt, g_Ett);

  __half *EttS[2], *w1sS[2], *w1eS[2], *w2sS[2], *w2eS[2], *m1S[2];
  {
    __half (*p)[(size_t)M_*512];
    cudaGetSymbolAddress((void**)&p, g_EttS);
    for (int s=0;s<2;s++) EttS[s] = p[s];
  }
  {
    __half (*p)[(size_t)HP_*512];
    cudaGetSymbolAddress((void**)&p, g_w1sS);
    for (int s=0;s<2;s++) w1sS[s] = p[s];
    cudaGetSymbolAddress((void**)&p, g_w1eS);
    for (int s=0;s<2;s++) w1eS[s] = p[s];
  }
  {
    __half (*p)[(size_t)HP_*256];
    cudaGetSymbolAddress((void**)&p, g_w2sS);
    for (int s=0;s<2;s++) w2sS[s] = p[s];
    cudaGetSymbolAddress((void**)&p, g_w2eS);
    for (int s=0;s<2;s++) w2eS[s] = p[s];
  }
  {
    __half (*p)[(size_t)M_*256];
    cudaGetSymbolAddress((void**)&p, g_m1S);
    for (int s=0;s<2;s++) m1S[s] = p[s];
  }

  cudaFuncSetAttribute(hgemm<0>, cudaFuncAttributeMaxDynamicSharedMemorySize, GEMM_SMEM);
  cudaFuncSetAttribute(hgemm<1>, cudaFuncAttributeMaxDynamicSharedMemorySize, GEMM_SMEM);

  transpose_kernel<<<dim3(16,16,32), dim3(32,8)>>>(enc);
  init_kernel<<<32,512>>>();

  // fp16 h/m splits
  split2_kernel<<<(M_*512+255)/256,256>>>(pEtt, 512, 512, EttS[0], EttS[1], M_*512);
  split2_kernel<<<(HP_*512+255)/256,256>>>(w1s, 768, 512, w1sS[0], w1sS[1], HP_*512);
  split2_kernel<<<(HP_*512+255)/256,256>>>(w1e, 768, 512, w1eS[0], w1eS[1], HP_*512);
  split2_kernel<<<(HP_*256+255)/256,256>>>(w2s, 256, 256, w2sS[0], w2sS[1], HP_*256);
  split2_kernel<<<(HP_*256+255)/256,256>>>(w2e, 256, 256, w2eS[0], w2eS[1], HP_*256);

  dim3 gG(HP_/128, M_/256);  // (32, 64)
  // G1: A = Et @ w1[:, :512]^T + b1  (iteration-independent)
  hgemm<0><<<gG,256,GEMM_SMEM>>>(pAs, HP_, EttS[0],EttS[1], w1sS[0],w1sS[1], b1s, 512);
  hgemm<0><<<gG,256,GEMM_SMEM>>>(pAe, HP_, EttS[0],EttS[1], w1eS[0],w1eS[1], b1e, 512);

  for (int it = 0; it < ITERS_; ++it){
    // ---- start net ----
    r_kernel<<<32,256>>>(WDs);
    c_kernel<<<dim3(16,32),256>>>(w1s);
    m1_kernel<<<M_,256>>>(pAs);
    hgemm<1><<<gG,256,GEMM_SMEM>>>(pm2, 256, m1S[0],m1S[1], w2sS[0],w2sS[1], b2s, 256);
    score_kernel<<<M_/8,256>>>(w3s, b3s);
    argmax_kernel<<<32,512>>>(lens, out_alphas + (size_t)it*B_*T_, out_start, pencs);
    // ---- end net ----
    r_kernel<<<32,256>>>(WDe);
    c_kernel<<<dim3(16,32),256>>>(w1e);
    m1_kernel<<<M_,256>>>(pAe);
    hgemm<1><<<gG,256,GEMM_SMEM>>>(pm2, 256, m1S[0],m1S[1], w2eS[0],w2eS[1], b2e, 256);
    score_kernel<<<M_/8,256>>>(w3e, b3e);
    argmax_kernel<<<32,512>>>(lens, out_betas + (size_t)it*B_*T_, out_end, pence);
    // ---- LSTM + MLP ----
    lstm_kernel<<<32,1024>>>(Wih, Whh, bih, bhh, Wmlp, bmlp);
  }
}

// round 4
// speedup vs baseline: 2.6789x; 1.3582x over previous
#include <cuda_runtime.h>
#include <cuda_fp16.h>
#include <math.h>
#include <stdint.h>

// Problem constants
#define B_   32
#define T_   512
#define H_   256
#define P_   16
#define M_   (B_*T_)     // 16384 rows
#define HP_  4096        // H*P
#define ITERS_ 4

// ================= device scratch (static, no allocation) =================
__device__ float g_Ett [(size_t)M_*512];
__device__ float g_m1  [(size_t)M_*H_];
__device__ float g_m2  [(size_t)M_*H_];
__device__ float g_scores[M_];
__device__ float g_c   [B_*HP_];
__device__ float g_encs[B_*512];
__device__ float g_ence[B_*512];
__device__ float g_hx  [B_*H_];
__device__ float g_cx  [B_*H_];

// fp16 operands
__device__ __half g_Etth [(size_t)M_*512];
__device__ __half g_Ah_s [(size_t)M_*HP_];   // A = Et@w1s[:, :512]^T + b1s (half)
__device__ __half g_Ah_e [(size_t)M_*HP_];
__device__ __half g_w1sh [(size_t)HP_*512];
__device__ __half g_w1eh [(size_t)HP_*512];
__device__ __half g_w1srh[(size_t)HP_*256];  // w1s[:, 512:768]
__device__ __half g_w1erh[(size_t)HP_*256];
__device__ __half g_w2sh [(size_t)HP_*256];
__device__ __half g_w2eh [(size_t)HP_*256];
__device__ __half g_m1h  [(size_t)M_*256];

// ================= helpers =================
__device__ __forceinline__ uint32_t smem_u32(const void* p){
  uint32_t a;
  asm("{ .reg .u64 t; cvta.to.shared.u64 t, %1; cvt.u32.u64 %0, t; }" : "=r"(a) : "l"(p));
  return a;
}
__device__ __forceinline__ void cpa16(uint32_t dst, const void* src){
  asm volatile("cp.async.cg.shared.global [%0], [%1], 16;" :: "r"(dst), "l"(src));
}
#define CP_COMMIT() asm volatile("cp.async.commit_group;" ::: "memory")
#define CP_WAIT2()  asm volatile("cp.async.wait_group 2;"  ::: "memory")

#define LDSM4(r, a) \
  asm volatile("ldmatrix.sync.aligned.m8n8.x4.shared.b16 {%0,%1,%2,%3}, [%4];" \
    : "=r"((r)[0]),"=r"((r)[1]),"=r"((r)[2]),"=r"((r)[3]) : "r"(a))

#define MMA16816(d, a, b0, b1) \
  asm volatile("mma.sync.aligned.m16n8k16.row.col.f32.f16.f16.f32 " \
    "{%0,%1,%2,%3}, {%4,%5,%6,%7}, {%8,%9}, {%0,%1,%2,%3};" \
    : "+f"((d)[0]),"+f"((d)[1]),"+f"((d)[2]),"+f"((d)[3]) \
    : "r"((a)[0]),"r"((a)[1]),"r"((a)[2]),"r"((a)[3]), "r"(b0),"r"(b1))

// ================= transpose: enc[B,2H,T] -> Ett[B*T, 2H] =================
__global__ void transpose_kernel(const float* __restrict__ enc){
  __shared__ float tile[32][33];
  int b  = blockIdx.z;
  int t0 = blockIdx.x*32, c0 = blockIdx.y*32;
  int x  = threadIdx.x;
  for (int i = threadIdx.y; i < 32; i += 8)
    tile[i][x] = enc[((size_t)b*512 + (c0+i))*512 + t0 + x];
  __syncthreads();
  for (int i = threadIdx.y; i < 32; i += 8)
    g_Ett[((size_t)b*512 + (t0+i))*512 + c0 + x] = tile[x][i];
}

__global__ void init_kernel(){
  int b = blockIdx.x, t = threadIdx.x;
  float v = g_Ett[((size_t)b*512)*512 + t];
  g_encs[b*512+t] = v;
  g_ence[b*512+t] = v;
  if (t < H_){ g_hx[b*H_+t] = 0.f; g_cx[b*H_+t] = 0.f; }
}

// ================= fp32 (strided) -> fp16 =================
__global__ void __launch_bounds__(256) cvt_kernel(const float* __restrict__ src, int ld, int cols,
                                                  __half* __restrict__ dst, int total)
{
  int idx = blockIdx.x*256 + threadIdx.x;
  if (idx >= total) return;
  int r = idx / cols, c = idx - r*cols;
  dst[idx] = __float2half_rn(src[(size_t)r*ld + c]);
}

// ================= single-pass HMMA GEMM: C[M,N] = A[M,K] @ B[N,K]^T =================
// CTA tile 256x128, 8 warps (4x2), warp tile 64x64. K-chunks of 16, 4-stage cp.async.
// EPI=0: bias + fp16 store (C half*, ldc). EPI=1: bias + maxout over 16-col groups (C float*, ldc=N/16).
#define STAGE_BYTES 12288   // A 8K | B 4K
#define NSTG 4
#define GEMM_SMEM (NSTG*STAGE_BYTES)

template<int EPI>
__global__ void __launch_bounds__(256, 1)
hgemm(void* __restrict__ Cv, int ldc,
      const __half* __restrict__ A, const __half* __restrict__ B,
      const float* __restrict__ bias, int K)
{
  extern __shared__ char smem[];
  uint32_t sb = smem_u32(smem);
  const int tid = threadIdx.x, lane = tid & 31, warp = tid >> 5;
  const int wm = warp >> 1, wn = warp & 1;
  const int row0 = blockIdx.y*256, col0 = blockIdx.x*128;
  const int nsteps = K >> 4;

  const __half* gA = A + (size_t)(row0 + tid)*K;
  const __half* gB = B + (size_t)(col0 + (tid>>1))*K + (tid&1)*8;
  const uint32_t swa = (tid>>2)&1;
  const uint32_t dA0 = 16*(tid*2 + swa);
  const uint32_t dA1 = 16*(tid*2 + (1u^swa));
  const uint32_t dB  = 16*((tid>>1)*2 + ((tid&1) ^ ((tid>>3)&1)));

  auto issue = [&](int s){
    uint32_t st = sb + (uint32_t)(s & (NSTG-1))*STAGE_BYTES;
    const __half* a0 = gA + s*16;
    cpa16(st+dA0, a0);
    cpa16(st+dA1, a0+8);
    cpa16(st+8192+dB, gB + s*16);
  };

  uint32_t aoff[4], boff[4];
  #pragma unroll
  for (int mi = 0; mi < 4; mi++){
    int r = wm*64 + mi*16 + (lane & 15);
    int c = lane >> 4;
    aoff[mi] = 16*(r*2 + (c ^ ((r>>2)&1)));
  }
  #pragma unroll
  for (int nj = 0; nj < 4; nj++){
    int n = wn*64 + nj*16 + (lane & 7) + ((lane>>4)<<3);
    int c = (lane>>3)&1;
    boff[nj] = 8192 + 16*(n*2 + (c ^ ((n>>2)&1)));
  }

  float acc[4][8][4];
  #pragma unroll
  for (int mi = 0; mi < 4; mi++)
    #pragma unroll
    for (int q = 0; q < 8; q++)
      #pragma unroll
      for (int v = 0; v < 4; v++) acc[mi][q][v] = 0.f;

  issue(0); CP_COMMIT();
  issue(1); CP_COMMIT();
  issue(2); CP_COMMIT();

  for (int i = 0; i < nsteps; i++){
    CP_WAIT2();
    __syncthreads();
    if (i+3 < nsteps) issue(i+3);
    CP_COMMIT();
    uint32_t st = sb + (uint32_t)(i & (NSTG-1))*STAGE_BYTES;

    uint32_t ah[4][4], bh[4][4];
    #pragma unroll
    for (int mi = 0; mi < 4; mi++) LDSM4(ah[mi], st + aoff[mi]);
    #pragma unroll
    for (int nj = 0; nj < 4; nj++) LDSM4(bh[nj], st + boff[nj]);
    #pragma unroll
    for (int mi = 0; mi < 4; mi++){
      #pragma unroll
      for (int q = 0; q < 8; q++){
        uint32_t b0 = bh[q>>1][(q&1)*2], b1 = bh[q>>1][(q&1)*2+1];
        MMA16816(acc[mi][q], ah[mi], b0, b1);
      }
    }
  }

  // epilogue
  #pragma unroll
  for (int mi = 0; mi < 4; mi++){
    int r0 = row0 + wm*64 + mi*16 + (lane>>2);
    int r1 = r0 + 8;
    if (EPI == 0){
      __half* C = (__half*)Cv;
      #pragma unroll
      for (int q = 0; q < 8; q++){
        int cb = col0 + wn*64 + q*8 + 2*(lane&3);
        float bv0 = __ldg(bias+cb), bv1 = __ldg(bias+cb+1);
        *(__half2*)(C + (size_t)r0*ldc + cb) = __floats2half2_rn(acc[mi][q][0]+bv0, acc[mi][q][1]+bv1);
        *(__half2*)(C + (size_t)r1*ldc + cb) = __floats2half2_rn(acc[mi][q][2]+bv0, acc[mi][q][3]+bv1);
      }
    } else {
      float* C = (float*)Cv;
      #pragma unroll
      for (int g = 0; g < 4; g++){
        int cb = col0 + wn*64 + g*16;
        int cA = cb + 2*(lane&3), cB = cb + 8 + 2*(lane&3);
        float bA0 = __ldg(bias+cA), bA1 = __ldg(bias+cA+1);
        float bB0 = __ldg(bias+cB), bB1 = __ldg(bias+cB+1);
        float v0 = fmaxf(fmaxf(acc[mi][2*g][0]+bA0, acc[mi][2*g][1]+bA1),
                         fmaxf(acc[mi][2*g+1][0]+bB0, acc[mi][2*g+1][1]+bB1));
        float v1 = fmaxf(fmaxf(acc[mi][2*g][2]+bA0, acc[mi][2*g][3]+bA1),
                         fmaxf(acc[mi][2*g+1][2]+bB0, acc[mi][2*g+1][3]+bB1));
        v0 = fmaxf(v0, __shfl_xor_sync(0xffffffffu, v0, 1));
        v0 = fmaxf(v0, __shfl_xor_sync(0xffffffffu, v0, 2));
        v1 = fmaxf(v1, __shfl_xor_sync(0xffffffffu, v1, 1));
        v1 = fmaxf(v1, __shfl_xor_sync(0xffffffffu, v1, 2));
        if ((lane & 3) == 0){
          C[(size_t)r0*ldc + (cb>>4)] = v0;
          C[(size_t)r1*ldc + (cb>>4)] = v1;
        }
      }
    }
  }
}

// ====== fused r+c: r = tanh([hx|enc_s|enc_e] @ WD^T); c[b,j] = r . w1r[j,:] ======
__global__ void __launch_bounds__(256) rc_kernel(const float* __restrict__ WD,
                                                 const __half* __restrict__ w1r){
  __shared__ float v[1280];
  __shared__ float rs[256];
  int b = blockIdx.x, tid = threadIdx.x;
  v[tid] = g_hx[b*H_+tid];
  for (int i = tid; i < 512; i += 256){
    v[256+i] = g_encs[b*512+i];
    v[768+i] = g_ence[b*512+i];
  }
  __syncthreads();
  {
    const float* w = WD + (size_t)tid*1280;
    float acc = 0.f;
    #pragma unroll 4
    for (int k = 0; k < 1280; k += 4){
      float4 wk = *(const float4*)(w+k);
      acc += wk.x*v[k] + wk.y*v[k+1] + wk.z*v[k+2] + wk.w*v[k+3];
    }
    rs[tid] = tanhf(acc);
  }
  __syncthreads();
  for (int j = tid; j < HP_; j += 256){
    const __half* wp = w1r + (size_t)j*256;
    float acc = 0.f;
    #pragma unroll 4
    for (int k = 0; k < 256; k += 8){
      uint4 u = *(const uint4*)(wp + k);
      __half2 h0 = *(__half2*)&u.x, h1 = *(__half2*)&u.y;
      __half2 h2 = *(__half2*)&u.z, h3 = *(__half2*)&u.w;
      acc += __low2float(h0)*rs[k]   + __high2float(h0)*rs[k+1]
           + __low2float(h1)*rs[k+2] + __high2float(h1)*rs[k+3]
           + __low2float(h2)*rs[k+4] + __high2float(h2)*rs[k+5]
           + __low2float(h3)*rs[k+6] + __high2float(h3)*rs[k+7];
    }
    g_c[b*HP_+j] = acc;
  }
}

// ====== m1[row,h] = max_p(A[row,h*16+p] + c[b,h*16+p]); write fp32 + fp16 ======
__global__ void __launch_bounds__(256) m1_kernel(const __half* __restrict__ A){
  int row = blockIdx.x, h = threadIdx.x, b = row >> 9;
  const __half2* ap = (const __half2*)(A   + (size_t)row*HP_ + h*16);
  const float4*  cp = (const float4*) (g_c + (size_t)b  *HP_ + h*16);
  float m = -3.0e38f;
  #pragma unroll
  for (int q = 0; q < 4; q++){
    float4 c = cp[q];
    __half2 a0 = ap[2*q], a1 = ap[2*q+1];
    m = fmaxf(m, fmaxf(fmaxf(__low2float(a0)+c.x, __high2float(a0)+c.y),
                       fmaxf(__low2float(a1)+c.z, __high2float(a1)+c.w)));
  }
  size_t o = (size_t)row*H_ + h;
  g_m1[o]  = m;
  g_m1h[o] = __float2half_rn(m);
}

// ================= scores[row] = max_p([m1|m2] . w3[p,:] + b3[p]) =================
__global__ void __launch_bounds__(256) score_kernel(const float* __restrict__ w3,
                                                   const float* __restrict__ b3){
  __shared__ float ws[16][512];
  int tid = threadIdx.x;
  for (int i = tid; i < 16*512; i += 256) ((float*)ws)[i] = w3[i];
  __syncthreads();
  int warp = tid >> 5, lane = tid & 31;
  size_t row = (size_t)blockIdx.x*8 + warp;
  const float* m1r = g_m1 + row*H_;
  const float* m2r = g_m2 + row*H_;
  float acc[16];
  #pragma unroll
  for (int p = 0; p < 16; p++) acc[p] = 0.f;
  #pragma unroll
  for (int kk = 0; kk < 512; kk += 128){
    int k = kk + lane*4;
    float4 x = (k < 256) ? *(const float4*)(m1r + k) : *(const float4*)(m2r + k - 256);
    #pragma unroll
    for (int p = 0; p < 16; p++){
      float4 wv = *(const float4*)&ws[p][k];
      acc[p] += x.x*wv.x + x.y*wv.y + x.z*wv.z + x.w*wv.w;
    }
  }
  #pragma unroll
  for (int p = 0; p < 16; p++)
    #pragma unroll
    for (int off = 16; off; off >>= 1)
      acc[p] += __shfl_xor_sync(0xffffffffu, acc[p], off);
  if (lane == 0){
    float m = -3.0e38f;
    #pragma unroll
    for (int p = 0; p < 16; p++) m = fmaxf(m, acc[p] + b3[p]);
    g_scores[row] = m;
  }
}

// ================= masked argmax + gather =================
__global__ void __launch_bounds__(512) argmax_kernel(const int* __restrict__ lens,
    float* __restrict__ alphas, float* __restrict__ idx_out, float* __restrict__ enc)
{
  __shared__ float sv[512];
  __shared__ int   si[512];
  int b = blockIdx.x, t = threadIdx.x;
  float s = g_scores[b*T_+t] - ((t < lens[b]) ? 0.f : 1.0e9f);
  alphas[(size_t)b*T_ + t] = s;
  sv[t] = s; si[t] = t;
  __syncthreads();
  for (int off = 256; off; off >>= 1){
    if (t < off){
      float v2 = sv[t+off]; int i2 = si[t+off];
      if (v2 > sv[t] || (v2 == sv[t] && i2 < si[t])) { sv[t] = v2; si[t] = i2; }
    }
    __syncthreads();
  }
  int idx = si[0];
  enc[b*512 + t] = g_Ett[((size_t)b*T_ + idx)*512 + t];
  if (t == 0) idx_out[b] = (float)idx;
}

// ================= LSTM cell + MLP =================
__global__ void __launch_bounds__(1024) lstm_kernel(
  const float* __restrict__ Wih, const float* __restrict__ Whh,
  const float* __restrict__ bih, const float* __restrict__ bhh,
  const float* __restrict__ Wmlp, const float* __restrict__ bmlp)
{
  __shared__ float xs[1024];
  __shared__ float hs[256];
  __shared__ float gsh[1024];
  __shared__ float hp[256];
  int b = blockIdx.x, tid = threadIdx.x;
  if (tid < 512) xs[tid] = g_encs[b*512+tid];
  else           xs[tid] = g_ence[b*512+tid-512];
  if (tid < 256) hs[tid] = g_hx[b*256+tid];
  __syncthreads();
  {
    const float* wi = Wih + (size_t)tid*1024;
    float acc = bih[tid] + bhh[tid];
    #pragma unroll 4
    for (int k = 0; k < 1024; k += 4){
      float4 w = *(const float4*)(wi+k);
      acc += w.x*xs[k] + w.y*xs[k+1] + w.z*xs[k+2] + w.w*xs[k+3];
    }
    const float* wh = Whh + (size_t)tid*256;
    #pragma unroll 4
    for (int k = 0; k < 256; k += 4){
      float4 w = *(const float4*)(wh+k);
      acc += w.x*hs[k] + w.y*hs[k+1] + w.z*hs[k+2] + w.w*hs[k+3];
    }
    gsh[tid] = acc;
  }
  __syncthreads();
  if (tid < 256){
    float i_ = 1.f/(1.f+expf(-gsh[tid]));
    float f_ = 1.f/(1.f+expf(-gsh[256+tid]));
    float gg = tanhf(gsh[512+tid]);
    float o_ = 1.f/(1.f+expf(-gsh[768+tid]));
    float c  = f_*g_cx[b*256+tid] + i_*gg;
    g_cx[b*256+tid] = c;
    hp[tid] = o_*tanhf(c);
  }
  __syncthreads();
  if (tid < 256){
    const float* wm = Wmlp + (size_t)tid*256;
    float acc = bmlp[tid];
    #pragma unroll 4
    for (int k = 0; k < 256; k += 4){
      float4 w = *(const float4*)(wm+k);
      acc += w.x*hp[k] + w.y*hp[k+1] + w.z*hp[k+2] + w.w*hp[k+3];
    }
    g_hx[b*256+tid] = acc;
  }
}

// ================= host orchestration =================
extern "C" void kernel_launch(void* const* d_in, const int* in_sizes, int n_in,
                              void* d_out, int out_size)
{
  (void)in_sizes; (void)n_in; (void)out_size;
  const float* enc =(const float*)d_in[0];
  const int*   lens=(const int*)  d_in[1];
  const float* WDs =(const float*)d_in[2];
  const float* w1s =(const float*)d_in[3];  const float* b1s=(const float*)d_in[4];
  const float* w2s =(const float*)d_in[5];  const float* b2s=(const float*)d_in[6];
  const float* w3s =(const float*)d_in[7];  const float* b3s=(const float*)d_in[8];
  const float* WDe =(const float*)d_in[9];
  const float* w1e =(const float*)d_in[10]; const float* b1e=(const float*)d_in[11];
  const float* w2e =(const float*)d_in[12]; const float* b2e=(const float*)d_in[13];
  const float* w3e =(const float*)d_in[14]; const float* b3e=(const float*)d_in[15];
  const float* Wih =(const float*)d_in[16]; const float* Whh=(const float*)d_in[17];
  const float* bih =(const float*)d_in[18]; const float* bhh=(const float*)d_in[19];
  const float* Wmlp=(const float*)d_in[20]; const float* bmlp=(const float*)d_in[21];

  float* out = (float*)d_out;
  float* out_start  = out;
  float* out_end    = out + 32;
  float* out_alphas = out + 64;
  float* out_betas  = out + 64 + (size_t)ITERS_*B_*T_;

  float *pEtt,*pm2,*pencs,*pence;
  cudaGetSymbolAddress((void**)&pEtt, g_Ett);
  cudaGetSymbolAddress((void**)&pm2,  g_m2);
  cudaGetSymbolAddress((void**)&pencs,g_encs);
  cudaGetSymbolAddress((void**)&pence,g_ence);

  __half *pEtth,*pAs,*pAe,*pw1sh,*pw1eh,*pw1srh,*pw1erh,*pw2sh,*pw2eh,*pm1h;
  cudaGetSymbolAddress((void**)&pEtth, g_Etth);
  cudaGetSymbolAddress((void**)&pAs,   g_Ah_s);
  cudaGetSymbolAddress((void**)&pAe,   g_Ah_e);
  cudaGetSymbolAddress((void**)&pw1sh, g_w1sh);
  cudaGetSymbolAddress((void**)&pw1eh, g_w1eh);
  cudaGetSymbolAddress((void**)&pw1srh,g_w1srh);
  cudaGetSymbolAddress((void**)&pw1erh,g_w1erh);
  cudaGetSymbolAddress((void**)&pw2sh, g_w2sh);
  cudaGetSymbolAddress((void**)&pw2eh, g_w2eh);
  cudaGetSymbolAddress((void**)&pm1h,  g_m1h);

  cudaFuncSetAttribute(hgemm<0>, cudaFuncAttributeMaxDynamicSharedMemorySize, GEMM_SMEM);
  cudaFuncSetAttribute(hgemm<1>, cudaFuncAttributeMaxDynamicSharedMemorySize, GEMM_SMEM);

  // Launch order arranged so ncu (-s 5 -c 1) captures the 6th launch = hgemm<0>.
  transpose_kernel<<<dim3(16,16,32), dim3(32,8)>>>(enc);                 // 1
  init_kernel<<<32,512>>>();                                            // 2
  cvt_kernel<<<(M_*512+255)/256,256>>>(pEtt, 512, 512, pEtth, M_*512);  // 3
  cvt_kernel<<<(HP_*512+255)/256,256>>>(w1s, 768, 512, pw1sh, HP_*512); // 4
  cvt_kernel<<<(HP_*512+255)/256,256>>>(w1e, 768, 512, pw1eh, HP_*512); // 5

  dim3 gG(HP_/128, M_/256);  // (32, 64)
  hgemm<0><<<gG,256,GEMM_SMEM>>>(pAs, HP_, pEtth, pw1sh, b1s, 512);     // 6 <- ncu
  hgemm<0><<<gG,256,GEMM_SMEM>>>(pAe, HP_, pEtth, pw1eh, b1e, 512);     // 7

  cvt_kernel<<<(HP_*256+255)/256,256>>>(w1s+512, 768, 256, pw1srh, HP_*256);
  cvt_kernel<<<(HP_*256+255)/256,256>>>(w1e+512, 768, 256, pw1erh, HP_*256);
  cvt_kernel<<<(HP_*256+255)/256,256>>>(w2s, 256, 256, pw2sh, HP_*256);
  cvt_kernel<<<(HP_*256+255)/256,256>>>(w2e, 256, 256, pw2eh, HP_*256);

  for (int it = 0; it < ITERS_; ++it){
    // ---- start net ----
    rc_kernel<<<32,256>>>(WDs, pw1srh);
    m1_kernel<<<M_,256>>>(pAs);
    hgemm<1><<<gG,256,GEMM_SMEM>>>(pm2, 256, pm1h, pw2sh, b2s, 256);
    score_kernel<<<M_/8,256>>>(w3s, b3s);
    argmax_kernel<<<32,512>>>(lens, out_alphas + (size_t)it*B_*T_, out_start, pencs);
    // ---- end net ----
    rc_kernel<<<32,256>>>(WDe, pw1erh);
    m1_kernel<<<M_,256>>>(pAe);
    hgemm<1><<<gG,256,GEMM_SMEM>>>(pm2, 256, pm1h, pw2eh, b2e, 256);
    score_kernel<<<M_/8,256>>>(w3e, b3e);
    argmax_kernel<<<32,512>>>(lens, out_betas + (size_t)it*B_*T_, out_end, pence);
    // ---- LSTM + MLP ----
    lstm_kernel<<<32,1024>>>(Wih, Whh, bih, bhh, Wmlp, bmlp);
  }
}

// round 8
// speedup vs baseline: 2.9818x; 1.1131x over previous
#include <cuda_runtime.h>
#include <cuda_fp16.h>
#include <math.h>
#include <stdint.h>

// Problem constants
#define B_   32
#define T_   512
#define H_   256
#define P_   16
#define M_   (B_*T_)     // 16384 rows
#define HP_  4096        // H*P
#define ITERS_ 4

// ================= device scratch (static, no allocation) =================
__device__ float g_Ett [(size_t)M_*512];
__device__ float g_m1  [(size_t)M_*H_];
__device__ float g_m2  [(size_t)M_*H_];
__device__ float g_scores[M_];
__device__ float g_c   [B_*HP_];
__device__ float g_r   [B_*H_];
__device__ float g_encs[B_*512];
__device__ float g_ence[B_*512];
__device__ float g_hx  [B_*H_];
__device__ float g_cx  [B_*H_];

// fp16 operands
__device__ __half g_Etth [(size_t)M_*512];
__device__ __half g_Ah_s [(size_t)M_*HP_];   // A = Et@w1s[:, :512]^T + b1s (half)
__device__ __half g_Ah_e [(size_t)M_*HP_];
__device__ __half g_w1sh [(size_t)HP_*512];
__device__ __half g_w1eh [(size_t)HP_*512];
__device__ __half g_w1srh[(size_t)HP_*256];  // w1[:, 512:768]
__device__ __half g_w1erh[(size_t)HP_*256];
__device__ __half g_w2sh [(size_t)HP_*256];
__device__ __half g_w2eh [(size_t)HP_*256];
__device__ __half g_m1h  [(size_t)M_*256];

// ================= helpers =================
__device__ __forceinline__ uint32_t smem_u32(const void* p){
  uint32_t a;
  asm("{ .reg .u64 t; cvta.to.shared.u64 t, %1; cvt.u32.u64 %0, t; }" : "=r"(a) : "l"(p));
  return a;
}
__device__ __forceinline__ void cpa16(uint32_t dst, const void* src){
  asm volatile("cp.async.cg.shared.global [%0], [%1], 16;" :: "r"(dst), "l"(src));
}
#define CP_COMMIT() asm volatile("cp.async.commit_group;" ::: "memory")
#define CP_WAIT2()  asm volatile("cp.async.wait_group 2;"  ::: "memory")

#define LDSM4(r, a) \
  asm volatile("ldmatrix.sync.aligned.m8n8.x4.shared.b16 {%0,%1,%2,%3}, [%4];" \
    : "=r"((r)[0]),"=r"((r)[1]),"=r"((r)[2]),"=r"((r)[3]) : "r"(a))

#define MMA16816(d, a, b0, b1) \
  asm volatile("mma.sync.aligned.m16n8k16.row.col.f32.f16.f16.f32 " \
    "{%0,%1,%2,%3}, {%4,%5,%6,%7}, {%8,%9}, {%0,%1,%2,%3};" \
    : "+f"((d)[0]),"+f"((d)[1]),"+f"((d)[2]),"+f"((d)[3]) \
    : "r"((a)[0]),"r"((a)[1]),"r"((a)[2]),"r"((a)[3]), "r"(b0),"r"(b1))

// ================= transpose: enc[B,2H,T] -> Ett[B*T, 2H] =================
__global__ void transpose_kernel(const float* __restrict__ enc){
  __shared__ float tile[32][33];
  int b  = blockIdx.z;
  int t0 = blockIdx.x*32, c0 = blockIdx.y*32;
  int x  = threadIdx.x;
  for (int i = threadIdx.y; i < 32; i += 8)
    tile[i][x] = enc[((size_t)b*512 + (c0+i))*512 + t0 + x];
  __syncthreads();
  for (int i = threadIdx.y; i < 32; i += 8)
    g_Ett[((size_t)b*512 + (t0+i))*512 + c0 + x] = tile[x][i];
}

__global__ void init_kernel(){
  int b = blockIdx.x, t = threadIdx.x;
  float v = g_Ett[((size_t)b*512)*512 + t];
  g_encs[b*512+t] = v;
  g_ence[b*512+t] = v;
  if (t < H_){ g_hx[b*H_+t] = 0.f; g_cx[b*H_+t] = 0.f; }
}

// ================= fp32 (strided) -> fp16 =================
__global__ void __launch_bounds__(256) cvt_kernel(const float* __restrict__ src, int ld, int cols,
                                                  __half* __restrict__ dst, int total)
{
  int idx = blockIdx.x*256 + threadIdx.x;
  if (idx >= total) return;
  int r = idx / cols, c = idx - r*cols;
  dst[idx] = __float2half_rn(src[(size_t)r*ld + c]);
}

// ================= HMMA GEMM (fp32 acc): C[M,N] = A[M,K] @ B[N,K]^T =================
// CTA tile 256x128, 8 warps (4x2), warp tile 64x64. K-chunks of 16, 4-stage cp.async.
// EPI=0: bias + fp16 store (C half*, ldc). EPI=1: bias + maxout over 16-col groups (C float*, ldc=N/16).
#define STAGE_BYTES 12288   // A 8K | B 4K
#define NSTG 4
#define GEMM_SMEM (NSTG*STAGE_BYTES)

template<int EPI>
__global__ void __launch_bounds__(256, 1)
hgemm(void* __restrict__ Cv, int ldc,
      const __half* __restrict__ A, const __half* __restrict__ B,
      const float* __restrict__ bias, int K)
{
  extern __shared__ char smem[];
  uint32_t sb = smem_u32(smem);
  const int tid = threadIdx.x, lane = tid & 31, warp = tid >> 5;
  const int wm = warp >> 1, wn = warp & 1;
  const int row0 = blockIdx.y*256, col0 = blockIdx.x*128;
  const int nsteps = K >> 4;

  const __half* gA = A + (size_t)(row0 + tid)*K;
  const __half* gB = B + (size_t)(col0 + (tid>>1))*K + (tid&1)*8;
  const uint32_t swa = (tid>>2)&1;
  const uint32_t dA0 = 16*(tid*2 + swa);
  const uint32_t dA1 = 16*(tid*2 + (1u^swa));
  const uint32_t dB  = 16*((tid>>1)*2 + ((tid&1) ^ ((tid>>3)&1)));

  auto issue = [&](int s){
    uint32_t st = sb + (uint32_t)(s & (NSTG-1))*STAGE_BYTES;
    const __half* a0 = gA + s*16;
    cpa16(st+dA0, a0);
    cpa16(st+dA1, a0+8);
    cpa16(st+8192+dB, gB + s*16);
  };

  uint32_t aoff[4], boff[4];
  #pragma unroll
  for (int mi = 0; mi < 4; mi++){
    int r = wm*64 + mi*16 + (lane & 15);
    int c = lane >> 4;
    aoff[mi] = 16*(r*2 + (c ^ ((r>>2)&1)));
  }
  #pragma unroll
  for (int nj = 0; nj < 4; nj++){
    int n = wn*64 + nj*16 + (lane & 7) + ((lane>>4)<<3);
    int c = (lane>>3)&1;
    boff[nj] = 8192 + 16*(n*2 + (c ^ ((n>>2)&1)));
  }

  float acc[4][8][4];
  #pragma unroll
  for (int mi = 0; mi < 4; mi++)
    #pragma unroll
    for (int q = 0; q < 8; q++)
      #pragma unroll
      for (int v = 0; v < 4; v++) acc[mi][q][v] = 0.f;

  issue(0); CP_COMMIT();
  issue(1); CP_COMMIT();
  issue(2); CP_COMMIT();

  for (int i = 0; i < nsteps; i++){
    CP_WAIT2();
    __syncthreads();
    if (i+3 < nsteps) issue(i+3);
    CP_COMMIT();
    uint32_t st = sb + (uint32_t)(i & (NSTG-1))*STAGE_BYTES;

    uint32_t ah[4][4], bh[4][4];
    #pragma unroll
    for (int mi = 0; mi < 4; mi++) LDSM4(ah[mi], st + aoff[mi]);
    #pragma unroll
    for (int nj = 0; nj < 4; nj++) LDSM4(bh[nj], st + boff[nj]);
    #pragma unroll
    for (int mi = 0; mi < 4; mi++){
      #pragma unroll
      for (int q = 0; q < 8; q++){
        uint32_t b0 = bh[q>>1][(q&1)*2], b1 = bh[q>>1][(q&1)*2+1];
        MMA16816(acc[mi][q], ah[mi], b0, b1);
      }
    }
  }

  // epilogue
  #pragma unroll
  for (int mi = 0; mi < 4; mi++){
    int r0 = row0 + wm*64 + mi*16 + (lane>>2);
    int r1 = r0 + 8;
    if (EPI == 0){
      __half* C = (__half*)Cv;
      #pragma unroll
      for (int q = 0; q < 8; q++){
        int cb = col0 + wn*64 + q*8 + 2*(lane&3);
        float bv0 = __ldg(bias+cb), bv1 = __ldg(bias+cb+1);
        *(__half2*)(C + (size_t)r0*ldc + cb) = __floats2half2_rn(acc[mi][q][0]+bv0, acc[mi][q][1]+bv1);
        *(__half2*)(C + (size_t)r1*ldc + cb) = __floats2half2_rn(acc[mi][q][2]+bv0, acc[mi][q][3]+bv1);
      }
    } else {
      float* C = (float*)Cv;
      #pragma unroll
      for (int g = 0; g < 4; g++){
        int cb = col0 + wn*64 + g*16;
        int cA = cb + 2*(lane&3), cB = cb + 8 + 2*(lane&3);
        float bA0 = __ldg(bias+cA), bA1 = __ldg(bias+cA+1);
        float bB0 = __ldg(bias+cB), bB1 = __ldg(bias+cB+1);
        float v0 = fmaxf(fmaxf(acc[mi][2*g][0]+bA0, acc[mi][2*g][1]+bA1),
                         fmaxf(acc[mi][2*g+1][0]+bB0, acc[mi][2*g+1][1]+bB1));
        float v1 = fmaxf(fmaxf(acc[mi][2*g][2]+bA0, acc[mi][2*g][3]+bA1),
                         fmaxf(acc[mi][2*g+1][2]+bB0, acc[mi][2*g+1][3]+bB1));
        v0 = fmaxf(v0, __shfl_xor_sync(0xffffffffu, v0, 1));
        v0 = fmaxf(v0, __shfl_xor_sync(0xffffffffu, v0, 2));
        v1 = fmaxf(v1, __shfl_xor_sync(0xffffffffu, v1, 1));
        v1 = fmaxf(v1, __shfl_xor_sync(0xffffffffu, v1, 2));
        if ((lane & 3) == 0){
          C[(size_t)r0*ldc + (cb>>4)] = v0;
          C[(size_t)r1*ldc + (cb>>4)] = v1;
        }
      }
    }
  }
}

// ================= r = tanh([hx|enc_s|enc_e] @ WD^T) =================
__global__ void __launch_bounds__(256) r_kernel(const float* __restrict__ WD){
  __shared__ float v[1280];
  int b = blockIdx.x, tid = threadIdx.x;
  v[tid] = g_hx[b*H_+tid];
  for (int i = tid; i < 512; i += 256){
    v[256+i] = g_encs[b*512+i];
    v[768+i] = g_ence[b*512+i];
  }
  __syncthreads();
  const float* w = WD + (size_t)tid*1280;
  float acc = 0.f;
  #pragma unroll 4
  for (int k = 0; k < 1280; k += 4){
    float4 wk = *(const float4*)(w+k);
    acc += wk.x*v[k] + wk.y*v[k+1] + wk.z*v[k+2] + wk.w*v[k+3];
  }
  g_r[b*H_+tid] = tanhf(acc);
}

// ====== c[b,j] = r[b,:] . w1r[j,:]  (half weights, fp32 accumulate) ======
__global__ void __launch_bounds__(256) c_kernel(const __half* __restrict__ w1r){
  __shared__ float rs[256];
  int b = blockIdx.y, j = blockIdx.x*256 + threadIdx.x;
  rs[threadIdx.x] = g_r[b*H_+threadIdx.x];
  __syncthreads();
  const __half* wp = w1r + (size_t)j*256;
  float acc = 0.f;
  #pragma unroll 4
  for (int k = 0; k < 256; k += 8){
    uint4 u = *(const uint4*)(wp + k);
    float2 f0 = __half22float2(*(__half2*)&u.x);
    float2 f1 = __half22float2(*(__half2*)&u.y);
    float2 f2 = __half22float2(*(__half2*)&u.z);
    float2 f3 = __half22float2(*(__half2*)&u.w);
    acc += f0.x*rs[k]   + f0.y*rs[k+1] + f1.x*rs[k+2] + f1.y*rs[k+3]
         + f2.x*rs[k+4] + f2.y*rs[k+5] + f3.x*rs[k+6] + f3.y*rs[k+7];
  }
  g_c[b*HP_+j] = acc;
}

// ====== m1[row,h] = max_p(A[row,h*16+p] + c[b,h*16+p]); write fp32 + fp16 ======
__global__ void __launch_bounds__(256) m1_kernel(const __half* __restrict__ A){
  int row = blockIdx.x, h = threadIdx.x, b = row >> 9;
  const __half2* ap = (const __half2*)(A   + (size_t)row*HP_ + h*16);
  const float4*  cp = (const float4*) (g_c + (size_t)b  *HP_ + h*16);
  float m = -3.0e38f;
  #pragma unroll
  for (int q = 0; q < 4; q++){
    float4 c = cp[q];
    __half2 a0 = ap[2*q], a1 = ap[2*q+1];
    m = fmaxf(m, fmaxf(fmaxf(__low2float(a0)+c.x, __high2float(a0)+c.y),
                       fmaxf(__low2float(a1)+c.z, __high2float(a1)+c.w)));
  }
  size_t o = (size_t)row*H_ + h;
  g_m1[o]  = m;
  g_m1h[o] = __float2half_rn(m);
}

// ====== scores[row] = max_p([m1|m2].w3[p,:] + b3[p]), lane-per-row, fp32 ======
__global__ void __launch_bounds__(128) score_kernel(const float* __restrict__ w3,
                                                    const float* __restrict__ b3){
  __shared__ float sw[16][512];
  int tid = threadIdx.x;
  for (int i = tid; i < 16*512; i += 128) ((float*)sw)[i] = w3[i];
  __syncthreads();
  int row = blockIdx.x*128 + tid;
  const float* m1r = g_m1 + (size_t)row*H_;
  const float* m2r = g_m2 + (size_t)row*H_;
  float acc[16];
  #pragma unroll
  for (int p = 0; p < 16; p++) acc[p] = 0.f;
  #pragma unroll 1
  for (int kc = 0; kc < 16; kc++){
    float x[32];
    const float* src = (kc < 8) ? (m1r + kc*32) : (m2r + (kc-8)*32);
    #pragma unroll
    for (int u = 0; u < 8; u++) *(float4*)(x + u*4) = *(const float4*)(src + u*4);
    int kb = kc*32;
    #pragma unroll
    for (int p = 0; p < 16; p++){
      float a = acc[p];
      #pragma unroll
      for (int j = 0; j < 32; j++) a += x[j]*sw[p][kb+j];
      acc[p] = a;
    }
  }
  float m = -3.0e38f;
  #pragma unroll
  for (int p = 0; p < 16; p++) m = fmaxf(m, acc[p] + __ldg(b3+p));
  g_scores[row] = m;
}

// ================= masked argmax + gather =================
__global__ void __launch_bounds__(512) argmax_kernel(const int* __restrict__ lens,
    float* __restrict__ alphas, float* __restrict__ idx_out, float* __restrict__ enc)
{
  __shared__ float sv[512];
  __shared__ int   si[512];
  int b = blockIdx.x, t = threadIdx.x;
  float s = g_scores[b*T_+t] - ((t < lens[b]) ? 0.f : 1.0e9f);
  alphas[(size_t)b*T_ + t] = s;
  sv[t] = s; si[t] = t;
  __syncthreads();
  for (int off = 256; off; off >>= 1){
    if (t < off){
      float v2 = sv[t+off]; int i2 = si[t+off];
      if (v2 > sv[t] || (v2 == sv[t] && i2 < si[t])) { sv[t] = v2; si[t] = i2; }
    }
    __syncthreads();
  }
  int idx = si[0];
  enc[b*512 + t] = g_Ett[((size_t)b*T_ + idx)*512 + t];
  if (t == 0) idx_out[b] = (float)idx;
}

// ================= LSTM cell + MLP =================
__global__ void __launch_bounds__(1024) lstm_kernel(
  const float* __restrict__ Wih, const float* __restrict__ Whh,
  const float* __restrict__ bih, const float* __restrict__ bhh,
  const float* __restrict__ Wmlp, const float* __restrict__ bmlp)
{
  __shared__ float xs[1024];
  __shared__ float hs[256];
  __shared__ float gsh[1024];
  __shared__ float hp[256];
  int b = blockIdx.x, tid = threadIdx.x;
  if (tid < 512) xs[tid] = g_encs[b*512+tid];
  else           xs[tid] = g_ence[b*512+tid-512];
  if (tid < 256) hs[tid] = g_hx[b*256+tid];
  __syncthreads();
  {
    const float* wi = Wih + (size_t)tid*1024;
    float acc = bih[tid] + bhh[tid];
    #pragma unroll 4
    for (int k = 0; k < 1024; k += 4){
      float4 w = *(const float4*)(wi+k);
      acc += w.x*xs[k] + w.y*xs[k+1] + w.z*xs[k+2] + w.w*xs[k+3];
    }
    const float* wh = Whh + (size_t)tid*256;
    #pragma unroll 4
    for (int k = 0; k < 256; k += 4){
      float4 w = *(const float4*)(wh+k);
      acc += w.x*hs[k] + w.y*hs[k+1] + w.z*hs[k+2] + w.w*hs[k+3];
    }
    gsh[tid] = acc;
  }
  __syncthreads();
  if (tid < 256){
    float i_ = 1.f/(1.f+expf(-gsh[tid]));
    float f_ = 1.f/(1.f+expf(-gsh[256+tid]));
    float gg = tanhf(gsh[512+tid]);
    float o_ = 1.f/(1.f+expf(-gsh[768+tid]));
    float c  = f_*g_cx[b*256+tid] + i_*gg;
    g_cx[b*256+tid] = c;
    hp[tid] = o_*tanhf(c);
  }
  __syncthreads();
  if (tid < 256){
    const float* wm = Wmlp + (size_t)tid*256;
    float acc = bmlp[tid];
    #pragma unroll 4
    for (int k = 0; k < 256; k += 4){
      float4 w = *(const float4*)(wm+k);
      acc += w.x*hp[k] + w.y*hp[k+1] + w.z*hp[k+2] + w.w*hp[k+3];
    }
    g_hx[b*256+tid] = acc;
  }
}

// ================= host orchestration =================
extern "C" void kernel_launch(void* const* d_in, const int* in_sizes, int n_in,
                              void* d_out, int out_size)
{
  (void)in_sizes; (void)n_in; (void)out_size;
  const float* enc =(const float*)d_in[0];
  const int*   lens=(const int*)  d_in[1];
  const float* WDs =(const float*)d_in[2];
  const float* w1s =(const float*)d_in[3];  const float* b1s=(const float*)d_in[4];
  const float* w2s =(const float*)d_in[5];  const float* b2s=(const float*)d_in[6];
  const float* w3s =(const float*)d_in[7];  const float* b3s=(const float*)d_in[8];
  const float* WDe =(const float*)d_in[9];
  const float* w1e =(const float*)d_in[10]; const float* b1e=(const float*)d_in[11];
  const float* w2e =(const float*)d_in[12]; const float* b2e=(const float*)d_in[13];
  const float* w3e =(const float*)d_in[14]; const float* b3e=(const float*)d_in[15];
  const float* Wih =(const float*)d_in[16]; const float* Whh=(const float*)d_in[17];
  const float* bih =(const float*)d_in[18]; const float* bhh=(const float*)d_in[19];
  const float* Wmlp=(const float*)d_in[20]; const float* bmlp=(const float*)d_in[21];

  float* out = (float*)d_out;
  float* out_start  = out;
  float* out_end    = out + 32;
  float* out_alphas = out + 64;
  float* out_betas  = out + 64 + (size_t)ITERS_*B_*T_;

  float *pEtt,*pm2,*pencs,*pence;
  cudaGetSymbolAddress((void**)&pEtt, g_Ett);
  cudaGetSymbolAddress((void**)&pm2,  g_m2);
  cudaGetSymbolAddress((void**)&pencs,g_encs);
  cudaGetSymbolAddress((void**)&pence,g_ence);

  __half *pEtth,*pAs,*pAe,*pw1sh,*pw1eh,*pw1srh,*pw1erh,*pw2sh,*pw2eh,*pm1h;
  cudaGetSymbolAddress((void**)&pEtth, g_Etth);
  cudaGetSymbolAddress((void**)&pAs,   g_Ah_s);
  cudaGetSymbolAddress((void**)&pAe,   g_Ah_e);
  cudaGetSymbolAddress((void**)&pw1sh, g_w1sh);
  cudaGetSymbolAddress((void**)&pw1eh, g_w1eh);
  cudaGetSymbolAddress((void**)&pw1srh,g_w1srh);
  cudaGetSymbolAddress((void**)&pw1erh,g_w1erh);
  cudaGetSymbolAddress((void**)&pw2sh, g_w2sh);
  cudaGetSymbolAddress((void**)&pw2eh, g_w2eh);
  cudaGetSymbolAddress((void**)&pm1h,  g_m1h);

  cudaFuncSetAttribute(hgemm<0>, cudaFuncAttributeMaxDynamicSharedMemorySize, GEMM_SMEM);
  cudaFuncSetAttribute(hgemm<1>, cudaFuncAttributeMaxDynamicSharedMemorySize, GEMM_SMEM);

  transpose_kernel<<<dim3(16,16,32), dim3(32,8)>>>(enc);
  init_kernel<<<32,512>>>();
  cvt_kernel<<<(M_*512+255)/256,256>>>(pEtt, 512, 512, pEtth, M_*512);
  cvt_kernel<<<(HP_*512+255)/256,256>>>(w1s, 768, 512, pw1sh, HP_*512);
  cvt_kernel<<<(HP_*512+255)/256,256>>>(w1e, 768, 512, pw1eh, HP_*512);

  dim3 gG(HP_/128, M_/256);  // (32, 64)
  hgemm<0><<<gG,256,GEMM_SMEM>>>(pAs, HP_, pEtth, pw1sh, b1s, 512);
  hgemm<0><<<gG,256,GEMM_SMEM>>>(pAe, HP_, pEtth, pw1eh, b1e, 512);

  cvt_kernel<<<(HP_*256+255)/256,256>>>(w1s+512, 768, 256, pw1srh, HP_*256);
  cvt_kernel<<<(HP_*256+255)/256,256>>>(w1e+512, 768, 256, pw1erh, HP_*256);
  cvt_kernel<<<(HP_*256+255)/256,256>>>(w2s, 256, 256, pw2sh, HP_*256);
  cvt_kernel<<<(HP_*256+255)/256,256>>>(w2e, 256, 256, pw2eh, HP_*256);

  for (int it = 0; it < ITERS_; ++it){
    // ---- start net ----
    r_kernel<<<32,256>>>(WDs);
    c_kernel<<<dim3(16,32),256>>>(pw1srh);
    m1_kernel<<<M_,256>>>(pAs);
    hgemm<1><<<gG,256,GEMM_SMEM>>>(pm2, 256, pm1h, pw2sh, b2s, 256);
    score_kernel<<<M_/128,128>>>(w3s, b3s);
    argmax_kernel<<<32,512>>>(lens, out_alphas + (size_t)it*B_*T_, out_start, pencs);
    // ---- end net ----
    r_kernel<<<32,256>>>(WDe);
    c_kernel<<<dim3(16,32),256>>>(pw1erh);
    m1_kernel<<<M_,256>>>(pAe);
    hgemm<1><<<gG,256,GEMM_SMEM>>>(pm2, 256, pm1h, pw2eh, b2e, 256);
    score_kernel<<<M_/128,128>>>(w3e, b3e);
    argmax_kernel<<<32,512>>>(lens, out_betas + (size_t)it*B_*T_, out_end, pence);
    // ---- LSTM + MLP ----
    lstm_kernel<<<32,1024>>>(Wih, Whh, bih, bhh, Wmlp, bmlp);
  }
}

// round 10
// speedup vs baseline: 3.4314x; 1.1508x over previous
#include <cuda_runtime.h>
#include <cuda_fp16.h>
#include <math.h>
#include <stdint.h>

// Problem constants
#define B_   32
#define T_   512
#define H_   256
#define P_   16
#define M_   (B_*T_)     // 16384 rows
#define HP_  4096        // H*P
#define ITERS_ 4

// ================= device scratch (static, no allocation) =================
__device__ float g_Ett [(size_t)M_*512];
__device__ float g_m1  [(size_t)M_*H_];
__device__ float g_m2  [(size_t)M_*H_];
__device__ float g_scores[M_];
__device__ float g_c   [B_*HP_];
__device__ float g_r   [B_*H_];
__device__ float g_encs[B_*512];
__device__ float g_ence[B_*512];
__device__ float g_hx  [B_*H_];
__device__ float g_cx  [B_*H_];

// fp16 operands
__device__ __half g_Etth [(size_t)M_*512];
__device__ __half g_Ah_s [(size_t)M_*HP_];   // A = Et@w1s[:, :512]^T + b1s (half)
__device__ __half g_Ah_e [(size_t)M_*HP_];
__device__ __half g_w1sh [(size_t)HP_*512];
__device__ __half g_w1eh [(size_t)HP_*512];
__device__ __half g_w1srh[(size_t)HP_*256];  // w1[:, 512:768]
__device__ __half g_w1erh[(size_t)HP_*256];
__device__ __half g_w2sh [(size_t)HP_*256];
__device__ __half g_w2eh [(size_t)HP_*256];
__device__ __half g_m1h  [(size_t)M_*256];

// ================= helpers =================
__device__ __forceinline__ uint32_t smem_u32(const void* p){
  uint32_t a;
  asm("{ .reg .u64 t; cvta.to.shared.u64 t, %1; cvt.u32.u64 %0, t; }" : "=r"(a) : "l"(p));
  return a;
}
__device__ __forceinline__ void cpa16(uint32_t dst, const void* src){
  asm volatile("cp.async.cg.shared.global [%0], [%1], 16;" :: "r"(dst), "l"(src));
}
#define CP_COMMIT() asm volatile("cp.async.commit_group;" ::: "memory")
#define CP_WAIT2()  asm volatile("cp.async.wait_group 2;"  ::: "memory")

#define LDSM4(r, a) \
  asm volatile("ldmatrix.sync.aligned.m8n8.x4.shared.b16 {%0,%1,%2,%3}, [%4];" \
    : "=r"((r)[0]),"=r"((r)[1]),"=r"((r)[2]),"=r"((r)[3]) : "r"(a))

#define MMA16816(d, a, b0, b1) \
  asm volatile("mma.sync.aligned.m16n8k16.row.col.f32.f16.f16.f32 " \
    "{%0,%1,%2,%3}, {%4,%5,%6,%7}, {%8,%9}, {%0,%1,%2,%3};" \
    : "+f"((d)[0]),"+f"((d)[1]),"+f"((d)[2]),"+f"((d)[3]) \
    : "r"((a)[0]),"r"((a)[1]),"r"((a)[2]),"r"((a)[3]), "r"(b0),"r"(b1))

// ================= transpose: enc[B,2H,T] -> Ett[B*T, 2H] =================
__global__ void transpose_kernel(const float* __restrict__ enc){
  __shared__ float tile[32][33];
  int b  = blockIdx.z;
  int t0 = blockIdx.x*32, c0 = blockIdx.y*32;
  int x  = threadIdx.x;
  for (int i = threadIdx.y; i < 32; i += 8)
    tile[i][x] = enc[((size_t)b*512 + (c0+i))*512 + t0 + x];
  __syncthreads();
  for (int i = threadIdx.y; i < 32; i += 8)
    g_Ett[((size_t)b*512 + (t0+i))*512 + c0 + x] = tile[x][i];
}

__global__ void init_kernel(){
  int b = blockIdx.x, t = threadIdx.x;
  float v = g_Ett[((size_t)b*512)*512 + t];
  g_encs[b*512+t] = v;
  g_ence[b*512+t] = v;
  if (t < H_){ g_hx[b*H_+t] = 0.f; g_cx[b*H_+t] = 0.f; }
}

// ================= fp32 (strided) -> fp16 =================
__global__ void __launch_bounds__(256) cvt_kernel(const float* __restrict__ src, int ld, int cols,
                                                  __half* __restrict__ dst, int total)
{
  int idx = blockIdx.x*256 + threadIdx.x;
  if (idx >= total) return;
  int r = idx / cols, c = idx - r*cols;
  dst[idx] = __float2half_rn(src[(size_t)r*ld + c]);
}

// ================= HMMA GEMM (fp32 acc): C[M,N] = A[M,K] @ B[N,K]^T =================
// CTA tile 256x128, 8 warps (4x2), warp tile 64x64. K-chunks of 16, 4-stage cp.async.
// EPI=0 only: bias + fp16 store. (G1 path — identical to the proven R8 kernel.)
#define STAGE_BYTES 12288   // A 8K | B 4K
#define NSTG 4
#define GEMM_SMEM (NSTG*STAGE_BYTES)

__global__ void __launch_bounds__(256, 1)
hgemm(__half* __restrict__ C, int ldc,
      const __half* __restrict__ A, const __half* __restrict__ B,
      const float* __restrict__ bias, int K)
{
  extern __shared__ char smem[];
  uint32_t sb = smem_u32(smem);
  const int tid = threadIdx.x, lane = tid & 31, warp = tid >> 5;
  const int wm = warp >> 1, wn = warp & 1;
  const int row0 = blockIdx.y*256, col0 = blockIdx.x*128;
  const int nsteps = K >> 4;

  const __half* gA = A + (size_t)(row0 + tid)*K;
  const __half* gB = B + (size_t)(col0 + (tid>>1))*K + (tid&1)*8;
  const uint32_t swa = (tid>>2)&1;
  const uint32_t dA0 = 16*(tid*2 + swa);
  const uint32_t dA1 = 16*(tid*2 + (1u^swa));
  const uint32_t dB  = 16*((tid>>1)*2 + ((tid&1) ^ ((tid>>3)&1)));

  auto issue = [&](int s){
    uint32_t st = sb + (uint32_t)(s & (NSTG-1))*STAGE_BYTES;
    const __half* a0 = gA + s*16;
    cpa16(st+dA0, a0);
    cpa16(st+dA1, a0+8);
    cpa16(st+8192+dB, gB + s*16);
  };

  uint32_t aoff[4], boff[4];
  #pragma unroll
  for (int mi = 0; mi < 4; mi++){
    int r = wm*64 + mi*16 + (lane & 15);
    int c = lane >> 4;
    aoff[mi] = 16*(r*2 + (c ^ ((r>>2)&1)));
  }
  #pragma unroll
  for (int nj = 0; nj < 4; nj++){
    int n = wn*64 + nj*16 + (lane & 7) + ((lane>>4)<<3);
    int c = (lane>>3)&1;
    boff[nj] = 8192 + 16*(n*2 + (c ^ ((n>>2)&1)));
  }

  float acc[4][8][4];
  #pragma unroll
  for (int mi = 0; mi < 4; mi++)
    #pragma unroll
    for (int q = 0; q < 8; q++)
      #pragma unroll
      for (int v = 0; v < 4; v++) acc[mi][q][v] = 0.f;

  issue(0); CP_COMMIT();
  issue(1); CP_COMMIT();
  issue(2); CP_COMMIT();

  for (int i = 0; i < nsteps; i++){
    CP_WAIT2();
    __syncthreads();
    if (i+3 < nsteps) issue(i+3);
    CP_COMMIT();
    uint32_t st = sb + (uint32_t)(i & (NSTG-1))*STAGE_BYTES;

    uint32_t ah[4][4], bh[4][4];
    #pragma unroll
    for (int mi = 0; mi < 4; mi++) LDSM4(ah[mi], st + aoff[mi]);
    #pragma unroll
    for (int nj = 0; nj < 4; nj++) LDSM4(bh[nj], st + boff[nj]);
    #pragma unroll
    for (int mi = 0; mi < 4; mi++){
      #pragma unroll
      for (int q = 0; q < 8; q++){
        uint32_t b0 = bh[q>>1][(q&1)*2], b1 = bh[q>>1][(q&1)*2+1];
        MMA16816(acc[mi][q], ah[mi], b0, b1);
      }
    }
  }

  #pragma unroll
  for (int mi = 0; mi < 4; mi++){
    int r0 = row0 + wm*64 + mi*16 + (lane>>2);
    int r1 = r0 + 8;
    #pragma unroll
    for (int q = 0; q < 8; q++){
      int cb = col0 + wn*64 + q*8 + 2*(lane&3);
      float bv0 = __ldg(bias+cb), bv1 = __ldg(bias+cb+1);
      *(__half2*)(C + (size_t)r0*ldc + cb) = __floats2half2_rn(acc[mi][q][0]+bv0, acc[mi][q][1]+bv1);
      *(__half2*)(C + (size_t)r1*ldc + cb) = __floats2half2_rn(acc[mi][q][2]+bv0, acc[mi][q][3]+bv1);
    }
  }
}

// ===== G2 GEMM: 128x128 tile, fp32 acc, maxout epilogue, masked-tile skip =====
// 8 warps (2x4), warp tile 64x32. Same fragment math / loaders as above.
#define STAGE_BYTES2 8192   // A 4K | B 4K
#define GEMM_SMEM2 (NSTG*STAGE_BYTES2)

__global__ void __launch_bounds__(256, 2)
hgemm_mx(float* __restrict__ C, int ldc,
         const __half* __restrict__ A, const __half* __restrict__ B,
         const float* __restrict__ bias, int K, const int* __restrict__ lens)
{
  const int row0 = blockIdx.y*128, col0 = blockIdx.x*128;
  // skip tiles whose 128 rows are entirely masked (t >= len for whole stripe)
  if ((row0 & 511) >= __ldg(lens + (row0 >> 9))) return;

  extern __shared__ char smem[];
  uint32_t sb = smem_u32(smem);
  const int tid = threadIdx.x, lane = tid & 31, warp = tid >> 5;
  const int wm = warp >> 2, wn = warp & 3;
  const int nsteps = K >> 4;

  const __half* gA = A + (size_t)(row0 + (tid>>1))*K + (tid&1)*8;
  const __half* gB = B + (size_t)(col0 + (tid>>1))*K + (tid&1)*8;
  const uint32_t dAB = 16*((tid>>1)*2 + ((tid&1) ^ ((tid>>3)&1)));

  auto issue = [&](int s){
    uint32_t st = sb + (uint32_t)(s & (NSTG-1))*STAGE_BYTES2;
    cpa16(st + dAB,        gA + s*16);
    cpa16(st + 4096 + dAB, gB + s*16);
  };

  uint32_t aoff[4], boff[2];
  #pragma unroll
  for (int mi = 0; mi < 4; mi++){
    int r = wm*64 + mi*16 + (lane & 15);
    int c = lane >> 4;
    aoff[mi] = 16*(r*2 + (c ^ ((r>>2)&1)));
  }
  #pragma unroll
  for (int nj = 0; nj < 2; nj++){
    int n = wn*32 + nj*16 + (lane & 7) + ((lane>>4)<<3);
    int c = (lane>>3)&1;
    boff[nj] = 4096 + 16*(n*2 + (c ^ ((n>>2)&1)));
  }

  float acc[4][4][4];
  #pragma unroll
  for (int mi = 0; mi < 4; mi++)
    #pragma unroll
    for (int q = 0; q < 4; q++)
      #pragma unroll
      for (int v = 0; v < 4; v++) acc[mi][q][v] = 0.f;

  issue(0); CP_COMMIT();
  issue(1); CP_COMMIT();
  issue(2); CP_COMMIT();

  for (int i = 0; i < nsteps; i++){
    CP_WAIT2();
    __syncthreads();
    if (i+3 < nsteps) issue(i+3);
    CP_COMMIT();
    uint32_t st = sb + (uint32_t)(i & (NSTG-1))*STAGE_BYTES2;

    uint32_t ah[4][4], bh[2][4];
    #pragma unroll
    for (int mi = 0; mi < 4; mi++) LDSM4(ah[mi], st + aoff[mi]);
    #pragma unroll
    for (int nj = 0; nj < 2; nj++) LDSM4(bh[nj], st + boff[nj]);
    #pragma unroll
    for (int mi = 0; mi < 4; mi++){
      #pragma unroll
      for (int q = 0; q < 4; q++){
        uint32_t b0 = bh[q>>1][(q&1)*2], b1 = bh[q>>1][(q&1)*2+1];
        MMA16816(acc[mi][q], ah[mi], b0, b1);
      }
    }
  }

  // maxout epilogue over 16-col groups -> C float, col index cb/16
  #pragma unroll
  for (int mi = 0; mi < 4; mi++){
    int r0 = row0 + wm*64 + mi*16 + (lane>>2);
    int r1 = r0 + 8;
    #pragma unroll
    for (int g = 0; g < 2; g++){
      int cb = col0 + wn*32 + g*16;
      int cA = cb + 2*(lane&3), cB = cb + 8 + 2*(lane&3);
      float bA0 = __ldg(bias+cA), bA1 = __ldg(bias+cA+1);
      float bB0 = __ldg(bias+cB), bB1 = __ldg(bias+cB+1);
      float v0 = fmaxf(fmaxf(acc[mi][2*g][0]+bA0, acc[mi][2*g][1]+bA1),
                       fmaxf(acc[mi][2*g+1][0]+bB0, acc[mi][2*g+1][1]+bB1));
      float v1 = fmaxf(fmaxf(acc[mi][2*g][2]+bA0, acc[mi][2*g][3]+bA1),
                       fmaxf(acc[mi][2*g+1][2]+bB0, acc[mi][2*g+1][3]+bB1));
      v0 = fmaxf(v0, __shfl_xor_sync(0xffffffffu, v0, 1));
      v0 = fmaxf(v0, __shfl_xor_sync(0xffffffffu, v0, 2));
      v1 = fmaxf(v1, __shfl_xor_sync(0xffffffffu, v1, 1));
      v1 = fmaxf(v1, __shfl_xor_sync(0xffffffffu, v1, 2));
      if ((lane & 3) == 0){
        C[(size_t)r0*ldc + (cb>>4)] = v0;
        C[(size_t)r1*ldc + (cb>>4)] = v1;
      }
    }
  }
}

// ================= r = tanh([hx|enc_s|enc_e] @ WD^T) =================
__global__ void __launch_bounds__(256) r_kernel(const float* __restrict__ WD){
  __shared__ float v[1280];
  int b = blockIdx.x, tid = threadIdx.x;
  v[tid] = g_hx[b*H_+tid];
  for (int i = tid; i < 512; i += 256){
    v[256+i] = g_encs[b*512+i];
    v[768+i] = g_ence[b*512+i];
  }
  __syncthreads();
  const float* w = WD + (size_t)tid*1280;
  float acc = 0.f;
  #pragma unroll 4
  for (int k = 0; k < 1280; k += 4){
    float4 wk = *(const float4*)(w+k);
    acc += wk.x*v[k] + wk.y*v[k+1] + wk.z*v[k+2] + wk.w*v[k+3];
  }
  g_r[b*H_+tid] = tanhf(acc);
}

// ====== c[b,j] = r[b,:] . w1r[j,:]  (half weights, fp32 accumulate) ======
__global__ void __launch_bounds__(256) c_kernel(const __half* __restrict__ w1r){
  __shared__ float rs[256];
  int b = blockIdx.y, j = blockIdx.x*256 + threadIdx.x;
  rs[threadIdx.x] = g_r[b*H_+threadIdx.x];
  __syncthreads();
  const __half* wp = w1r + (size_t)j*256;
  float acc = 0.f;
  #pragma unroll 4
  for (int k = 0; k < 256; k += 8){
    uint4 u = *(const uint4*)(wp + k);
    float2 f0 = __half22float2(*(__half2*)&u.x);
    float2 f1 = __half22float2(*(__half2*)&u.y);
    float2 f2 = __half22float2(*(__half2*)&u.z);
    float2 f3 = __half22float2(*(__half2*)&u.w);
    acc += f0.x*rs[k]   + f0.y*rs[k+1] + f1.x*rs[k+2] + f1.y*rs[k+3]
         + f2.x*rs[k+4] + f2.y*rs[k+5] + f3.x*rs[k+6] + f3.y*rs[k+7];
  }
  g_c[b*HP_+j] = acc;
}

// ====== m1[row,h] = max_p(A[row,h*16+p] + c[b,h*16+p]); write fp32 + fp16 ======
__global__ void __launch_bounds__(256) m1_kernel(const __half* __restrict__ A,
                                                 const int* __restrict__ lens){
  int row = blockIdx.x, h = threadIdx.x, b = row >> 9;
  if ((row & 511) >= __ldg(lens + b)) return;   // masked row: skip
  const __half2* ap = (const __half2*)(A   + (size_t)row*HP_ + h*16);
  const float4*  cp = (const float4*) (g_c + (size_t)b  *HP_ + h*16);
  float m = -3.0e38f;
  #pragma unroll
  for (int q = 0; q < 4; q++){
    float4 c = cp[q];
    __half2 a0 = ap[2*q], a1 = ap[2*q+1];
    m = fmaxf(m, fmaxf(fmaxf(__low2float(a0)+c.x, __high2float(a0)+c.y),
                       fmaxf(__low2float(a1)+c.z, __high2float(a1)+c.w)));
  }
  size_t o = (size_t)row*H_ + h;
  g_m1[o]  = m;
  g_m1h[o] = __float2half_rn(m);
}

// ====== scores[row] = max_p([m1|m2].w3[p,:] + b3[p]), lane-per-row, fp32 ======
__global__ void __launch_bounds__(128) score_kernel(const float* __restrict__ w3,
                                                    const float* __restrict__ b3,
                                                    const int* __restrict__ lens){
  __shared__ float sw[16][512];
  int tid = threadIdx.x;
  for (int i = tid; i < 16*512; i += 128) ((float*)sw)[i] = w3[i];
  __syncthreads();
  int row = blockIdx.x*128 + tid;
  if ((row & 511) >= __ldg(lens + (row >> 9))) return;  // masked row: skip
  const float* m1r = g_m1 + (size_t)row*H_;
  const float* m2r = g_m2 + (size_t)row*H_;
  float acc[16];
  #pragma unroll
  for (int p = 0; p < 16; p++) acc[p] = 0.f;
  #pragma unroll 1
  for (int kc = 0; kc < 16; kc++){
    float x[32];
    const float* src = (kc < 8) ? (m1r + kc*32) : (m2r + (kc-8)*32);
    #pragma unroll
    for (int u = 0; u < 8; u++) *(float4*)(x + u*4) = *(const float4*)(src + u*4);
    int kb = kc*32;
    #pragma unroll
    for (int p = 0; p < 16; p++){
      float a = acc[p];
      #pragma unroll
      for (int j = 0; j < 32; j++) a += x[j]*sw[p][kb+j];
      acc[p] = a;
    }
  }
  float m = -3.0e38f;
  #pragma unroll
  for (int p = 0; p < 16; p++) m = fmaxf(m, acc[p] + __ldg(b3+p));
  g_scores[row] = m;
}

// ================= masked argmax + gather =================
__global__ void __launch_bounds__(512) argmax_kernel(const int* __restrict__ lens,
    float* __restrict__ alphas, float* __restrict__ idx_out, float* __restrict__ enc)
{
  __shared__ float sv[512];
  __shared__ int   si[512];
  int b = blockIdx.x, t = threadIdx.x;
  // masked positions: exact -1e9 constant (never read stale scores)
  float s = (t < lens[b]) ? g_scores[b*T_+t] : -1.0e9f;
  alphas[(size_t)b*T_ + t] = s;
  sv[t] = s; si[t] = t;
  __syncthreads();
  for (int off = 256; off; off >>= 1){
    if (t < off){
      float v2 = sv[t+off]; int i2 = si[t+off];
      if (v2 > sv[t] || (v2 == sv[t] && i2 < si[t])) { sv[t] = v2; si[t] = i2; }
    }
    __syncthreads();
  }
  int idx = si[0];
  enc[b*512 + t] = g_Ett[((size_t)b*T_ + idx)*512 + t];
  if (t == 0) idx_out[b] = (float)idx;
}

// ================= LSTM cell + MLP =================
__global__ void __launch_bounds__(1024) lstm_kernel(
  const float* __restrict__ Wih, const float* __restrict__ Whh,
  const float* __restrict__ bih, const float* __restrict__ bhh,
  const float* __restrict__ Wmlp, const float* __restrict__ bmlp)
{
  __shared__ float xs[1024];
  __shared__ float hs[256];
  __shared__ float gsh[1024];
  __shared__ float hp[256];
  int b = blockIdx.x, tid = threadIdx.x;
  if (tid < 512) xs[tid] = g_encs[b*512+tid];
  else           xs[tid] = g_ence[b*512+tid-512];
  if (tid < 256) hs[tid] = g_hx[b*256+tid];
  __syncthreads();
  {
    const float* wi = Wih + (size_t)tid*1024;
    float acc = bih[tid] + bhh[tid];
    #pragma unroll 4
    for (int k = 0; k < 1024; k += 4){
      float4 w = *(const float4*)(wi+k);
      acc += w.x*xs[k] + w.y*xs[k+1] + w.z*xs[k+2] + w.w*xs[k+3];
    }
    const float* wh = Whh + (size_t)tid*256;
    #pragma unroll 4
    for (int k = 0; k < 256; k += 4){
      float4 w = *(const float4*)(wh+k);
      acc += w.x*hs[k] + w.y*hs[k+1] + w.z*hs[k+2] + w.w*hs[k+3];
    }
    gsh[tid] = acc;
  }
  __syncthreads();
  if (tid < 256){
    float i_ = 1.f/(1.f+expf(-gsh[tid]));
    float f_ = 1.f/(1.f+expf(-gsh[256+tid]));
    float gg = tanhf(gsh[512+tid]);
    float o_ = 1.f/(1.f+expf(-gsh[768+tid]));
    float c  = f_*g_cx[b*256+tid] + i_*gg;
    g_cx[b*256+tid] = c;
    hp[tid] = o_*tanhf(c);
  }
  __syncthreads();
  if (tid < 256){
    const float* wm = Wmlp + (size_t)tid*256;
    float acc = bmlp[tid];
    #pragma unroll 4
    for (int k = 0; k < 256; k += 4){
      float4 w = *(const float4*)(wm+k);
      acc += w.x*hp[k] + w.y*hp[k+1] + w.z*hp[k+2] + w.w*hp[k+3];
    }
    g_hx[b*256+tid] = acc;
  }
}

// ================= host orchestration =================
extern "C" void kernel_launch(void* const* d_in, const int* in_sizes, int n_in,
                              void* d_out, int out_size)
{
  (void)in_sizes; (void)n_in; (void)out_size;
  const float* enc =(const float*)d_in[0];
  const int*   lens=(const int*)  d_in[1];
  const float* WDs =(const float*)d_in[2];
  const float* w1s =(const float*)d_in[3];  const float* b1s=(const float*)d_in[4];
  const float* w2s =(const float*)d_in[5];  const float* b2s=(const float*)d_in[6];
  const float* w3s =(const float*)d_in[7];  const float* b3s=(const float*)d_in[8];
  const float* WDe =(const float*)d_in[9];
  const float* w1e =(const float*)d_in[10]; const float* b1e=(const float*)d_in[11];
  const float* w2e =(const float*)d_in[12]; const float* b2e=(const float*)d_in[13];
  const float* w3e =(const float*)d_in[14]; const float* b3e=(const float*)d_in[15];
  const float* Wih =(const float*)d_in[16]; const float* Whh=(const float*)d_in[17];
  const float* bih =(const float*)d_in[18]; const float* bhh=(const float*)d_in[19];
  const float* Wmlp=(const float*)d_in[20]; const float* bmlp=(const float*)d_in[21];

  float* out = (float*)d_out;
  float* out_start  = out;
  float* out_end    = out + 32;
  float* out_alphas = out + 64;
  float* out_betas  = out + 64 + (size_t)ITERS_*B_*T_;

  float *pEtt,*pm2,*pencs,*pence;
  cudaGetSymbolAddress((void**)&pEtt, g_Ett);
  cudaGetSymbolAddress((void**)&pm2,  g_m2);
  cudaGetSymbolAddress((void**)&pencs,g_encs);
  cudaGetSymbolAddress((void**)&pence,g_ence);

  __half *pEtth,*pAs,*pAe,*pw1sh,*pw1eh,*pw1srh,*pw1erh,*pw2sh,*pw2eh,*pm1h;
  cudaGetSymbolAddress((void**)&pEtth, g_Etth);
  cudaGetSymbolAddress((void**)&pAs,   g_Ah_s);
  cudaGetSymbolAddress((void**)&pAe,   g_Ah_e);
  cudaGetSymbolAddress((void**)&pw1sh, g_w1sh);
  cudaGetSymbolAddress((void**)&pw1eh, g_w1eh);
  cudaGetSymbolAddress((void**)&pw1srh,g_w1srh);
  cudaGetSymbolAddress((void**)&pw1erh,g_w1erh);
  cudaGetSymbolAddress((void**)&pw2sh, g_w2sh);
  cudaGetSymbolAddress((void**)&pw2eh, g_w2eh);
  cudaGetSymbolAddress((void**)&pm1h,  g_m1h);

  cudaFuncSetAttribute(hgemm,    cudaFuncAttributeMaxDynamicSharedMemorySize, GEMM_SMEM);
  cudaFuncSetAttribute(hgemm_mx, cudaFuncAttributeMaxDynamicSharedMemorySize, GEMM_SMEM2);

  dim3 gG1(HP_/128, M_/256);   // (32, 64)  — G1, 256-row tiles
  dim3 gG2(HP_/128, M_/128);   // (32, 128) — G2, 128-row tiles w/ skip

  // Launch order: our 5th launch = hgemm (G1) so the ncu capture slot lands on it.
  transpose_kernel<<<dim3(16,16,32), dim3(32,8)>>>(enc);                 // 1
  cvt_kernel<<<(M_*512+255)/256,256>>>(pEtt, 512, 512, pEtth, M_*512);  // 2
  cvt_kernel<<<(HP_*512+255)/256,256>>>(w1s, 768, 512, pw1sh, HP_*512); // 3
  init_kernel<<<32,512>>>();                                            // 4
  hgemm<<<gG1,256,GEMM_SMEM>>>(pAs, HP_, pEtth, pw1sh, b1s, 512);       // 5 <- ncu
  cvt_kernel<<<(HP_*512+255)/256,256>>>(w1e, 768, 512, pw1eh, HP_*512); // 6
  hgemm<<<gG1,256,GEMM_SMEM>>>(pAe, HP_, pEtth, pw1eh, b1e, 512);       // 7

  cvt_kernel<<<(HP_*256+255)/256,256>>>(w1s+512, 768, 256, pw1srh, HP_*256);
  cvt_kernel<<<(HP_*256+255)/256,256>>>(w1e+512, 768, 256, pw1erh, HP_*256);
  cvt_kernel<<<(HP_*256+255)/256,256>>>(w2s, 256, 256, pw2sh, HP_*256);
  cvt_kernel<<<(HP_*256+255)/256,256>>>(w2e, 256, 256, pw2eh, HP_*256);

  for (int it = 0; it < ITERS_; ++it){
    // ---- start net ----
    r_kernel<<<32,256>>>(WDs);
    c_kernel<<<dim3(16,32),256>>>(pw1srh);
    m1_kernel<<<M_,256>>>(pAs, lens);
    hgemm_mx<<<gG2,256,GEMM_SMEM2>>>(pm2, 256, pm1h, pw2sh, b2s, 256, lens);
    score_kernel<<<M_/128,128>>>(w3s, b3s, lens);
    argmax_kernel<<<32,512>>>(lens, out_alphas + (size_t)it*B_*T_, out_start, pencs);
    // ---- end net ----
    r_kernel<<<32,256>>>(WDe);
    c_kernel<<<dim3(16,32),256>>>(pw1erh);
    m1_kernel<<<M_,256>>>(pAe, lens);
    hgemm_mx<<<gG2,256,GEMM_SMEM2>>>(pm2, 256, pm1h, pw2eh, b2e, 256, lens);
    score_kernel<<<M_/128,128>>>(w3e, b3e, lens);
    argmax_kernel<<<32,512>>>(lens, out_betas + (size_t)it*B_*T_, out_end, pence);
    // ---- LSTM + MLP ----
    lstm_kernel<<<32,1024>>>(Wih, Whh, bih, bhh, Wmlp, bmlp);
  }
}

// round 14
// speedup vs baseline: 3.5959x; 1.0479x over previous
#include <cuda_runtime.h>
#include <cuda_fp16.h>
#include <math.h>
#include <stdint.h>

// Problem constants
#define B_   32
#define T_   512
#define H_   256
#define P_   16
#define M_   (B_*T_)     // 16384 rows
#define HP_  4096        // H*P
#define ITERS_ 4

// ================= device scratch (static, no allocation) =================
__device__ float g_Ett [(size_t)M_*512];
__device__ float g_m1  [(size_t)M_*H_];
__device__ float g_m2  [(size_t)M_*H_];
__device__ float g_scores[M_];
__device__ float g_c   [B_*HP_];
__device__ float g_r   [B_*H_];
__device__ float g_encs[B_*512];
__device__ float g_ence[B_*512];
__device__ float g_hx  [B_*H_];
__device__ float g_cx  [B_*H_];

// fp16 operands
__device__ __half g_Etth [(size_t)M_*512];
__device__ __half g_Ah_s [(size_t)M_*HP_];   // A = Et@w1s[:, :512]^T + b1s (half)
__device__ __half g_Ah_e [(size_t)M_*HP_];
__device__ __half g_w1sh [(size_t)HP_*512];
__device__ __half g_w1eh [(size_t)HP_*512];
__device__ __half g_w1srh[(size_t)HP_*256];  // w1[:, 512:768]
__device__ __half g_w1erh[(size_t)HP_*256];
__device__ __half g_w2sh [(size_t)HP_*256];
__device__ __half g_w2eh [(size_t)HP_*256];
__device__ __half g_m1h  [(size_t)M_*256];

// ================= helpers =================
__device__ __forceinline__ uint32_t smem_u32(const void* p){
  uint32_t a;
  asm("{ .reg .u64 t; cvta.to.shared.u64 t, %1; cvt.u32.u64 %0, t; }" : "=r"(a) : "l"(p));
  return a;
}
__device__ __forceinline__ void cpa16(uint32_t dst, const void* src){
  asm volatile("cp.async.cg.shared.global [%0], [%1], 16;" :: "r"(dst), "l"(src));
}
#define CP_COMMIT() asm volatile("cp.async.commit_group;" ::: "memory")
#define CP_WAIT2()  asm volatile("cp.async.wait_group 2;"  ::: "memory")

#define LDSM4(r, a) \
  asm volatile("ldmatrix.sync.aligned.m8n8.x4.shared.b16 {%0,%1,%2,%3}, [%4];" \
    : "=r"((r)[0]),"=r"((r)[1]),"=r"((r)[2]),"=r"((r)[3]) : "r"(a))

#define MMA16816(d, a, b0, b1) \
  asm volatile("mma.sync.aligned.m16n8k16.row.col.f32.f16.f16.f32 " \
    "{%0,%1,%2,%3}, {%4,%5,%6,%7}, {%8,%9}, {%0,%1,%2,%3};" \
    : "+f"((d)[0]),"+f"((d)[1]),"+f"((d)[2]),"+f"((d)[3]) \
    : "r"((a)[0]),"r"((a)[1]),"r"((a)[2]),"r"((a)[3]), "r"(b0),"r"(b1))

// ========= transpose: enc[B,2H,T] -> Ett[B*T, 2H] (fp32 + fp16) =========
__global__ void transpose_kernel(const float* __restrict__ enc){
  __shared__ float tile[32][33];
  int b  = blockIdx.z;
  int t0 = blockIdx.x*32, c0 = blockIdx.y*32;
  int x  = threadIdx.x;
  for (int i = threadIdx.y; i < 32; i += 8)
    tile[i][x] = enc[((size_t)b*512 + (c0+i))*512 + t0 + x];
  __syncthreads();
  for (int i = threadIdx.y; i < 32; i += 8){
    float v = tile[x][i];
    size_t o = ((size_t)b*512 + (t0+i))*512 + c0 + x;
    g_Ett[o]  = v;
    g_Etth[o] = __float2half_rn(v);
  }
}

__global__ void init_kernel(){
  int b = blockIdx.x, t = threadIdx.x;
  float v = g_Ett[((size_t)b*512)*512 + t];
  g_encs[b*512+t] = v;
  g_ence[b*512+t] = v;
  if (t < H_){ g_hx[b*H_+t] = 0.f; g_cx[b*H_+t] = 0.f; }
}

// ================= fp32 (strided) -> fp16 =================
__global__ void __launch_bounds__(256) cvt_kernel(const float* __restrict__ src, int ld, int cols,
                                                  __half* __restrict__ dst, int total)
{
  int idx = blockIdx.x*256 + threadIdx.x;
  if (idx >= total) return;
  int r = idx / cols, c = idx - r*cols;
  dst[idx] = __float2half_rn(src[(size_t)r*ld + c]);
}

// ===== Unified HMMA GEMM (fp32 acc): 128x128 tile, masked-stripe skip =====
// 8 warps (2x4), warp tile 64x32. K-chunks of 16, 4-stage cp.async.
// EPI=0: bias + fp16 store (C half*, ldc).  EPI=1: bias + maxout/16 (C float*, ldc).
#define STAGE_BYTES 8192    // A 4K | B 4K
#define NSTG 4
#define GEMM_SMEM (NSTG*STAGE_BYTES)

template<int EPI>
__global__ void __launch_bounds__(256, 2)
hgemm128(void* __restrict__ Cv, int ldc,
         const __half* __restrict__ A, const __half* __restrict__ B,
         const float* __restrict__ bias, int K, const int* __restrict__ lens)
{
  const int row0 = blockIdx.y*128, col0 = blockIdx.x*128;
  if ((row0 & 511) >= __ldg(lens + (row0 >> 9))) return;   // fully-masked stripe

  extern __shared__ char smem[];
  uint32_t sb = smem_u32(smem);
  const int tid = threadIdx.x, lane = tid & 31, warp = tid >> 5;
  const int wm = warp >> 2, wn = warp & 3;
  const int nsteps = K >> 4;

  const __half* gA = A + (size_t)(row0 + (tid>>1))*K + (tid&1)*8;
  const __half* gB = B + (size_t)(col0 + (tid>>1))*K + (tid&1)*8;
  const uint32_t dAB = 16*((tid>>1)*2 + ((tid&1) ^ ((tid>>3)&1)));

  auto issue = [&](int s){
    uint32_t st = sb + (uint32_t)(s & (NSTG-1))*STAGE_BYTES;
    cpa16(st + dAB,        gA + s*16);
    cpa16(st + 4096 + dAB, gB + s*16);
  };

  uint32_t aoff[4], boff[2];
  #pragma unroll
  for (int mi = 0; mi < 4; mi++){
    int r = wm*64 + mi*16 + (lane & 15);
    int c = lane >> 4;
    aoff[mi] = 16*(r*2 + (c ^ ((r>>2)&1)));
  }
  #pragma unroll
  for (int nj = 0; nj < 2; nj++){
    int n = wn*32 + nj*16 + (lane & 7) + ((lane>>4)<<3);
    int c = (lane>>3)&1;
    boff[nj] = 4096 + 16*(n*2 + (c ^ ((n>>2)&1)));
  }

  float acc[4][4][4];
  #pragma unroll
  for (int mi = 0; mi < 4; mi++)
    #pragma unroll
    for (int q = 0; q < 4; q++)
      #pragma unroll
      for (int v = 0; v < 4; v++) acc[mi][q][v] = 0.f;

  issue(0); CP_COMMIT();
  issue(1); CP_COMMIT();
  issue(2); CP_COMMIT();

  for (int i = 0; i < nsteps; i++){
    CP_WAIT2();
    __syncthreads();
    if (i+3 < nsteps) issue(i+3);
    CP_COMMIT();
    uint32_t st = sb + (uint32_t)(i & (NSTG-1))*STAGE_BYTES;

    uint32_t ah[4][4], bh[2][4];
    #pragma unroll
    for (int mi = 0; mi < 4; mi++) LDSM4(ah[mi], st + aoff[mi]);
    #pragma unroll
    for (int nj = 0; nj < 2; nj++) LDSM4(bh[nj], st + boff[nj]);
    #pragma unroll
    for (int mi = 0; mi < 4; mi++){
      #pragma unroll
      for (int q = 0; q < 4; q++){
        uint32_t b0 = bh[q>>1][(q&1)*2], b1 = bh[q>>1][(q&1)*2+1];
        MMA16816(acc[mi][q], ah[mi], b0, b1);
      }
    }
  }

  #pragma unroll
  for (int mi = 0; mi < 4; mi++){
    int r0 = row0 + wm*64 + mi*16 + (lane>>2);
    int r1 = r0 + 8;
    if (EPI == 0){
      __half* C = (__half*)Cv;
      #pragma unroll
      for (int q = 0; q < 4; q++){
        int cb = col0 + wn*32 + q*8 + 2*(lane&3);
        float bv0 = __ldg(bias+cb), bv1 = __ldg(bias+cb+1);
        *(__half2*)(C + (size_t)r0*ldc + cb) = __floats2half2_rn(acc[mi][q][0]+bv0, acc[mi][q][1]+bv1);
        *(__half2*)(C + (size_t)r1*ldc + cb) = __floats2half2_rn(acc[mi][q][2]+bv0, acc[mi][q][3]+bv1);
      }
    } else {
      float* C = (float*)Cv;
      #pragma unroll
      for (int g = 0; g < 2; g++){
        int cb = col0 + wn*32 + g*16;
        int cA = cb + 2*(lane&3), cB = cb + 8 + 2*(lane&3);
        float bA0 = __ldg(bias+cA), bA1 = __ldg(bias+cA+1);
        float bB0 = __ldg(bias+cB), bB1 = __ldg(bias+cB+1);
        float v0 = fmaxf(fmaxf(acc[mi][2*g][0]+bA0, acc[mi][2*g][1]+bA1),
                         fmaxf(acc[mi][2*g+1][0]+bB0, acc[mi][2*g+1][1]+bB1));
        float v1 = fmaxf(fmaxf(acc[mi][2*g][2]+bA0, acc[mi][2*g][3]+bA1),
                         fmaxf(acc[mi][2*g+1][2]+bB0, acc[mi][2*g+1][3]+bB1));
        v0 = fmaxf(v0, __shfl_xor_sync(0xffffffffu, v0, 1));
        v0 = fmaxf(v0, __shfl_xor_sync(0xffffffffu, v0, 2));
        v1 = fmaxf(v1, __shfl_xor_sync(0xffffffffu, v1, 1));
        v1 = fmaxf(v1, __shfl_xor_sync(0xffffffffu, v1, 2));
        if ((lane & 3) == 0){
          C[(size_t)r0*ldc + (cb>>4)] = v0;
          C[(size_t)r1*ldc + (cb>>4)] = v1;
        }
      }
    }
  }
}

// ================= r = tanh([hx|enc_s|enc_e] @ WD^T) =================
__global__ void __launch_bounds__(256) r_kernel(const float* __restrict__ WD){
  __shared__ float v[1280];
  int b = blockIdx.x, tid = threadIdx.x;
  v[tid] = g_hx[b*H_+tid];
  for (int i = tid; i < 512; i += 256){
    v[256+i] = g_encs[b*512+i];
    v[768+i] = g_ence[b*512+i];
  }
  __syncthreads();
  const float* w = WD + (size_t)tid*1280;
  float acc = 0.f;
  #pragma unroll 4
  for (int k = 0; k < 1280; k += 4){
    float4 wk = *(const float4*)(w+k);
    acc += wk.x*v[k] + wk.y*v[k+1] + wk.z*v[k+2] + wk.w*v[k+3];
  }
  g_r[b*H_+tid] = tanhf(acc);
}

// ====== c[b,j] = r[b,:] . w1r[j,:]  (half weights, fp32 accumulate) ======
__global__ void __launch_bounds__(256) c_kernel(const __half* __restrict__ w1r){
  __shared__ float rs[256];
  int b = blockIdx.y, j = blockIdx.x*256 + threadIdx.x;
  rs[threadIdx.x] = g_r[b*H_+threadIdx.x];
  __syncthreads();
  const __half* wp = w1r + (size_t)j*256;
  float acc = 0.f;
  #pragma unroll 4
  for (int k = 0; k < 256; k += 8){
    uint4 u = *(const uint4*)(wp + k);
    float2 f0 = __half22float2(*(__half2*)&u.x);
    float2 f1 = __half22float2(*(__half2*)&u.y);
    float2 f2 = __half22float2(*(__half2*)&u.z);
    float2 f3 = __half22float2(*(__half2*)&u.w);
    acc += f0.x*rs[k]   + f0.y*rs[k+1] + f1.x*rs[k+2] + f1.y*rs[k+3]
         + f2.x*rs[k+4] + f2.y*rs[k+5] + f3.x*rs[k+6] + f3.y*rs[k+7];
  }
  g_c[b*HP_+j] = acc;
}

// ====== m1[row,h] = max_p(A[row,h*16+p] + c[b,h*16+p]); write fp32 + fp16 ======
__global__ void __launch_bounds__(256) m1_kernel(const __half* __restrict__ A,
                                                 const int* __restrict__ lens){
  int row = blockIdx.x, h = threadIdx.x, b = row >> 9;
  if ((row & 511) >= __ldg(lens + b)) return;   // masked row: skip
  const __half2* ap = (const __half2*)(A   + (size_t)row*HP_ + h*16);
  const float4*  cp = (const float4*) (g_c + (size_t)b  *HP_ + h*16);
  float m = -3.0e38f;
  #pragma unroll
  for (int q = 0; q < 4; q++){
    float4 c = cp[q];
    __half2 a0 = ap[2*q], a1 = ap[2*q+1];
    m = fmaxf(m, fmaxf(fmaxf(__low2float(a0)+c.x, __high2float(a0)+c.y),
                       fmaxf(__low2float(a1)+c.z, __high2float(a1)+c.w)));
  }
  size_t o = (size_t)row*H_ + h;
  g_m1[o]  = m;
  g_m1h[o] = __float2half_rn(m);
}

// ====== scores[row] = max_p([m1|m2].w3[p,:] + b3[p]), lane-per-row, fp32 ======
__global__ void __launch_bounds__(128) score_kernel(const float* __restrict__ w3,
                                                    const float* __restrict__ b3,
                                                    const int* __restrict__ lens){
  __shared__ float sw[16][512];
  int tid = threadIdx.x;
  for (int i = tid; i < 16*512; i += 128) ((float*)sw)[i] = w3[i];
  __syncthreads();
  int row = blockIdx.x*128 + tid;
  if ((row & 511) >= __ldg(lens + (row >> 9))) return;  // masked row: skip
  const float* m1r = g_m1 + (size_t)row*H_;
  const float* m2r = g_m2 + (size_t)row*H_;
  float acc[16];
  #pragma unroll
  for (int p = 0; p < 16; p++) acc[p] = 0.f;
  #pragma unroll 1
  for (int kc = 0; kc < 16; kc++){
    float x[32];
    const float* src = (kc < 8) ? (m1r + kc*32) : (m2r + (kc-8)*32);
    #pragma unroll
    for (int u = 0; u < 8; u++) *(float4*)(x + u*4) = *(const float4*)(src + u*4);
    int kb = kc*32;
    #pragma unroll
    for (int p = 0; p < 16; p++){
      float a = acc[p];
      #pragma unroll
      for (int j = 0; j < 32; j++) a += x[j]*sw[p][kb+j];
      acc[p] = a;
    }
  }
  float m = -3.0e38f;
  #pragma unroll
  for (int p = 0; p < 16; p++) m = fmaxf(m, acc[p] + __ldg(b3+p));
  g_scores[row] = m;
}

// ========= masked argmax (first-index) + gather, shfl reduction =========
__global__ void __launch_bounds__(512) argmax_kernel(const int* __restrict__ lens,
    float* __restrict__ alphas, float* __restrict__ idx_out, float* __restrict__ enc)
{
  __shared__ float wv[16];
  __shared__ int   wi[16];
  __shared__ int   s_idx;
  int b = blockIdx.x, t = threadIdx.x;
  int lane = t & 31, warp = t >> 5;
  float s = (t < lens[b]) ? g_scores[b*T_+t] : -1.0e9f;
  alphas[(size_t)b*T_ + t] = s;
  float v = s; int idx = t;
  #pragma unroll
  for (int off = 16; off; off >>= 1){
    float v2 = __shfl_xor_sync(0xffffffffu, v, off);
    int   i2 = __shfl_xor_sync(0xffffffffu, idx, off);
    if (v2 > v || (v2 == v && i2 < idx)){ v = v2; idx = i2; }
  }
  if (lane == 0){ wv[warp] = v; wi[warp] = idx; }
  __syncthreads();
  if (warp == 0){
    v = (lane < 16) ? wv[lane] : -3.0e38f;
    idx = (lane < 16) ? wi[lane] : 0x7fffffff;
    #pragma unroll
    for (int off = 16; off; off >>= 1){
      float v2 = __shfl_xor_sync(0xffffffffu, v, off);
      int   i2 = __shfl_xor_sync(0xffffffffu, idx, off);
      if (v2 > v || (v2 == v && i2 < idx)){ v = v2; idx = i2; }
    }
    if (lane == 0){ s_idx = idx; if (b >= 0) idx_out[b] = (float)idx; }
  }
  __syncthreads();
  int gi = s_idx;
  enc[b*512 + t] = g_Ett[((size_t)b*T_ + gi)*512 + t];
}

// ================= LSTM cell + MLP =================
__global__ void __launch_bounds__(1024) lstm_kernel(
  const float* __restrict__ Wih, const float* __restrict__ Whh,
  const float* __restrict__ bih, const float* __restrict__ bhh,
  const float* __restrict__ Wmlp, const float* __restrict__ bmlp)
{
  __shared__ float xs[1024];
  __shared__ float hs[256];
  __shared__ float gsh[1024];
  __shared__ float hp[256];
  int b = blockIdx.x, tid = threadIdx.x;
  if (tid < 512) xs[tid] = g_encs[b*512+tid];
  else           xs[tid] = g_ence[b*512+tid-512];
  if (tid < 256) hs[tid] = g_hx[b*256+tid];
  __syncthreads();
  {
    const float* wi = Wih + (size_t)tid*1024;
    float acc = bih[tid] + bhh[tid];
    #pragma unroll 4
    for (int k = 0; k < 1024; k += 4){
      float4 w = *(const float4*)(wi+k);
      acc += w.x*xs[k] + w.y*xs[k+1] + w.z*xs[k+2] + w.w*xs[k+3];
    }
    const float* wh = Whh + (size_t)tid*256;
    #pragma unroll 4
    for (int k = 0; k < 256; k += 4){
      float4 w = *(const float4*)(wh+k);
      acc += w.x*hs[k] + w.y*hs[k+1] + w.z*hs[k+2] + w.w*hs[k+3];
    }
    gsh[tid] = acc;
  }
  __syncthreads();
  if (tid < 256){
    float i_ = 1.f/(1.f+expf(-gsh[tid]));
    float f_ = 1.f/(1.f+expf(-gsh[256+tid]));
    float gg = tanhf(gsh[512+tid]);
    float o_ = 1.f/(1.f+expf(-gsh[768+tid]));
    float c  = f_*g_cx[b*256+tid] + i_*gg;
    g_cx[b*256+tid] = c;
    hp[tid] = o_*tanhf(c);
  }
  __syncthreads();
  if (tid < 256){
    const float* wm = Wmlp + (size_t)tid*256;
    float acc = bmlp[tid];
    #pragma unroll 4
    for (int k = 0; k < 256; k += 4){
      float4 w = *(const float4*)(wm+k);
      acc += w.x*hp[k] + w.y*hp[k+1] + w.z*hp[k+2] + w.w*hp[k+3];
    }
    g_hx[b*256+tid] = acc;
  }
}

// ================= host orchestration =================
extern "C" void kernel_launch(void* const* d_in, const int* in_sizes, int n_in,
                              void* d_out, int out_size)
{
  (void)in_sizes; (void)n_in; (void)out_size;
  const float* enc =(const float*)d_in[0];
  const int*   lens=(const int*)  d_in[1];
  const float* WDs =(const float*)d_in[2];
  const float* w1s =(const float*)d_in[3];  const float* b1s=(const float*)d_in[4];
  const float* w2s =(const float*)d_in[5];  const float* b2s=(const float*)d_in[6];
  const float* w3s =(const float*)d_in[7];  const float* b3s=(const float*)d_in[8];
  const float* WDe =(const float*)d_in[9];
  const float* w1e =(const float*)d_in[10]; const float* b1e=(const float*)d_in[11];
  const float* w2e =(const float*)d_in[12]; const float* b2e=(const float*)d_in[13];
  const float* w3e =(const float*)d_in[14]; const float* b3e=(const float*)d_in[15];
  const float* Wih =(const float*)d_in[16]; const float* Whh=(const float*)d_in[17];
  const float* bih =(const float*)d_in[18]; const float* bhh=(const float*)d_in[19];
  const float* Wmlp=(const float*)d_in[20]; const float* bmlp=(const float*)d_in[21];

  float* out = (float*)d_out;
  float* out_start  = out;
  float* out_end    = out + 32;
  float* out_alphas = out + 64;
  float* out_betas  = out + 64 + (size_t)ITERS_*B_*T_;

  float *pm2,*pencs,*pence;
  cudaGetSymbolAddress((void**)&pm2,  g_m2);
  cudaGetSymbolAddress((void**)&pencs,g_encs);
  cudaGetSymbolAddress((void**)&pence,g_ence);

  __half *pEtth,*pAs,*pAe,*pw1sh,*pw1eh,*pw1srh,*pw1erh,*pw2sh,*pw2eh,*pm1h;
  cudaGetSymbolAddress((void**)&pEtth, g_Etth);
  cudaGetSymbolAddress((void**)&pAs,   g_Ah_s);
  cudaGetSymbolAddress((void**)&pAe,   g_Ah_e);
  cudaGetSymbolAddress((void**)&pw1sh, g_w1sh);
  cudaGetSymbolAddress((void**)&pw1eh, g_w1eh);
  cudaGetSymbolAddress((void**)&pw1srh,g_w1srh);
  cudaGetSymbolAddress((void**)&pw1erh,g_w1erh);
  cudaGetSymbolAddress((void**)&pw2sh, g_w2sh);
  cudaGetSymbolAddress((void**)&pw2eh, g_w2eh);
  cudaGetSymbolAddress((void**)&pm1h,  g_m1h);

  cudaFuncSetAttribute(hgemm128<0>, cudaFuncAttributeMaxDynamicSharedMemorySize, GEMM_SMEM);
  cudaFuncSetAttribute(hgemm128<1>, cudaFuncAttributeMaxDynamicSharedMemorySize, GEMM_SMEM);

  dim3 gG(HP_/128, M_/128);   // (32, 128) — both G1 and G2 geometry

  // Launch order: 5th launch = hgemm128<0> (G1) for the ncu capture slot.
  transpose_kernel<<<dim3(16,16,32), dim3(32,8)>>>(enc);                 // 1
  cvt_kernel<<<(HP_*512+255)/256,256>>>(w1s, 768, 512, pw1sh, HP_*512); // 2
  init_kernel<<<32,512>>>();                                            // 3
  cvt_kernel<<<(HP_*512+255)/256,256>>>(w1e, 768, 512, pw1eh, HP_*512); // 4
  hgemm128<0><<<gG,256,GEMM_SMEM>>>(pAs, HP_, pEtth, pw1sh, b1s, 512, lens); // 5 <- ncu
  hgemm128<0><<<gG,256,GEMM_SMEM>>>(pAe, HP_, pEtth, pw1eh, b1e, 512, lens); // 6

  cvt_kernel<<<(HP_*256+255)/256,256>>>(w1s+512, 768, 256, pw1srh, HP_*256);
  cvt_kernel<<<(HP_*256+255)/256,256>>>(w1e+512, 768, 256, pw1erh, HP_*256);
  cvt_kernel<<<(HP_*256+255)/256,256>>>(w2s, 256, 256, pw2sh, HP_*256);
  cvt_kernel<<<(HP_*256+255)/256,256>>>(w2e, 256, 256, pw2eh, HP_*256);

  for (int it = 0; it < ITERS_; ++it){
    // ---- start net ----
    r_kernel<<<32,256>>>(WDs);
    c_kernel<<<dim3(16,32),256>>>(pw1srh);
    m1_kernel<<<M_,256>>>(pAs, lens);
    hgemm128<1><<<gG,256,GEMM_SMEM>>>(pm2, 256, pm1h, pw2sh, b2s, 256, lens);
    score_kernel<<<M_/128,128>>>(w3s, b3s, lens);
    argmax_kernel<<<32,512>>>(lens, out_alphas + (size_t)it*B_*T_, out_start, pencs);
    // ---- end net ----
    r_kernel<<<32,256>>>(WDe);
    c_kernel<<<dim3(16,32),256>>>(pw1erh);
    m1_kernel<<<M_,256>>>(pAe, lens);
    hgemm128<1><<<gG,256,GEMM_SMEM>>>(pm2, 256, pm1h, pw2eh, b2e, 256, lens);
    score_kernel<<<M_/128,128>>>(w3e, b3e, lens);
    argmax_kernel<<<32,512>>>(lens, out_betas + (size_t)it*B_*T_, out_end, pence);
    // ---- LSTM + MLP ----
    lstm_kernel<<<32,1024>>>(Wih, Whh, bih, bhh, Wmlp, bmlp);
  }
}

// round 15
// speedup vs baseline: 3.8057x; 1.0583x over previous
#include <cuda_runtime.h>
#include <cuda_fp16.h>
#include <math.h>
#include <stdint.h>

// Problem constants
#define B_   32
#define T_   512
#define H_   256
#define P_   16
#define M_   (B_*T_)     // 16384 rows
#define HP_  4096        // H*P
#define ITERS_ 4

// ================= device scratch (static, no allocation) =================
__device__ float g_Ett [(size_t)M_*512];
__device__ float g_m1  [(size_t)M_*H_];
__device__ float g_m2  [(size_t)M_*H_];
__device__ float g_scores[M_];
__device__ float g_c   [B_*HP_];
__device__ float g_r   [B_*H_];
__device__ float g_encs[B_*512];
__device__ float g_ence[B_*512];
__device__ float g_hx  [B_*H_];
__device__ float g_cx  [B_*H_];

// row compaction (valid rows first; entries >= nvalid stay 0 = safe row)
__device__ int g_rowmap[M_];
__device__ int g_nvalid;

// fp16 operands
__device__ __half g_Etth [(size_t)M_*512];
__device__ __half g_Ah_s [(size_t)M_*HP_];   // A = Et@w1s[:, :512]^T + b1s (half, COMPACTED rows)
__device__ __half g_Ah_e [(size_t)M_*HP_];
__device__ __half g_w1sh [(size_t)HP_*512];
__device__ __half g_w1eh [(size_t)HP_*512];
__device__ __half g_w1srh[(size_t)HP_*256];  // w1[:, 512:768]
__device__ __half g_w1erh[(size_t)HP_*256];
__device__ __half g_w2sh [(size_t)HP_*256];
__device__ __half g_w2eh [(size_t)HP_*256];
__device__ __half g_m1h  [(size_t)M_*256];   // compacted rows

// ================= helpers =================
__device__ __forceinline__ uint32_t smem_u32(const void* p){
  uint32_t a;
  asm("{ .reg .u64 t; cvta.to.shared.u64 t, %1; cvt.u32.u64 %0, t; }" : "=r"(a) : "l"(p));
  return a;
}
__device__ __forceinline__ void cpa16(uint32_t dst, const void* src){
  asm volatile("cp.async.cg.shared.global [%0], [%1], 16;" :: "r"(dst), "l"(src));
}
#define CP_COMMIT() asm volatile("cp.async.commit_group;" ::: "memory")
#define CP_WAIT2()  asm volatile("cp.async.wait_group 2;"  ::: "memory")

#define LDSM4(r, a) \
  asm volatile("ldmatrix.sync.aligned.m8n8.x4.shared.b16 {%0,%1,%2,%3}, [%4];" \
    : "=r"((r)[0]),"=r"((r)[1]),"=r"((r)[2]),"=r"((r)[3]) : "r"(a))

#define MMA16816(d, a, b0, b1) \
  asm volatile("mma.sync.aligned.m16n8k16.row.col.f32.f16.f16.f32 " \
    "{%0,%1,%2,%3}, {%4,%5,%6,%7}, {%8,%9}, {%0,%1,%2,%3};" \
    : "+f"((d)[0]),"+f"((d)[1]),"+f"((d)[2]),"+f"((d)[3]) \
    : "r"((a)[0]),"r"((a)[1]),"r"((a)[2]),"r"((a)[3]), "r"(b0),"r"(b1))

// ========= transpose: enc[B,2H,T] -> Ett[B*T, 2H] (fp32 + fp16) =========
__global__ void transpose_kernel(const float* __restrict__ enc){
  __shared__ float tile[32][33];
  int b  = blockIdx.z;
  int t0 = blockIdx.x*32, c0 = blockIdx.y*32;
  int x  = threadIdx.x;
  for (int i = threadIdx.y; i < 32; i += 8)
    tile[i][x] = enc[((size_t)b*512 + (c0+i))*512 + t0 + x];
  __syncthreads();
  for (int i = threadIdx.y; i < 32; i += 8){
    float v = tile[x][i];
    size_t o = ((size_t)b*512 + (t0+i))*512 + c0 + x;
    g_Ett[o]  = v;
    g_Etth[o] = __float2half_rn(v);
  }
}

__global__ void init_kernel(){
  int b = blockIdx.x, t = threadIdx.x;
  float v = g_Ett[((size_t)b*512)*512 + t];
  g_encs[b*512+t] = v;
  g_ence[b*512+t] = v;
  if (t < H_){ g_hx[b*H_+t] = 0.f; g_cx[b*H_+t] = 0.f; }
}

// ========= rowmap: compact valid rows (t < len[b]) to the front =========
__global__ void rowmap_kernel(const int* __restrict__ lens){
  __shared__ int start;
  int b = blockIdx.x, t = threadIdx.x;   // 32 blocks x 512
  if (t == 0){
    int s = 0;
    for (int i = 0; i < b; i++) s += lens[i];
    start = s;
    if (b == 0){
      int tot = 0;
      for (int i = 0; i < B_; i++) tot += lens[i];
      g_nvalid = tot;
    }
  }
  __syncthreads();
  if (t < lens[b]) g_rowmap[start + t] = b*512 + t;
}

// ================= fp32 (strided) -> fp16 =================
__global__ void __launch_bounds__(256) cvt_kernel(const float* __restrict__ src, int ld, int cols,
                                                  __half* __restrict__ dst, int total)
{
  int idx = blockIdx.x*256 + threadIdx.x;
  if (idx >= total) return;
  int r = idx / cols, c = idx - r*cols;
  dst[idx] = __float2half_rn(src[(size_t)r*ld + c]);
}

// ===== Unified HMMA GEMM (fp32 acc): 128x128 tile over COMPACTED rows =====
// 8 warps (2x4), warp tile 64x32. K-chunks of 16, 4-stage cp.async.
// MAP=1: A rows gathered through g_rowmap (G1). MAP=0: A already compacted-dense (G2).
// EPI=0: bias + fp16 store (C half*, ldc).  EPI=1: bias + maxout/16 (C float*, ldc).
#define STAGE_BYTES 8192    // A 4K | B 4K
#define NSTG 4
#define GEMM_SMEM (NSTG*STAGE_BYTES)

template<int EPI, int MAP>
__global__ void __launch_bounds__(256, 2)
hgemm128(void* __restrict__ Cv, int ldc,
         const __half* __restrict__ A, const __half* __restrict__ B,
         const float* __restrict__ bias, int K)
{
  const int row0 = blockIdx.y*128, col0 = blockIdx.x*128;
  if (row0 >= g_nvalid) return;   // tile fully beyond compacted valid rows

  extern __shared__ char smem[];
  uint32_t sb = smem_u32(smem);
  const int tid = threadIdx.x, lane = tid & 31, warp = tid >> 5;
  const int wm = warp >> 2, wn = warp & 3;
  const int nsteps = K >> 4;

  int ar = row0 + (tid>>1);
  if (MAP) ar = __ldg(&g_rowmap[ar]);   // entries >= nvalid are 0 -> safe
  const __half* gA = A + (size_t)ar*K + (tid&1)*8;
  const __half* gB = B + (size_t)(col0 + (tid>>1))*K + (tid&1)*8;
  const uint32_t dAB = 16*((tid>>1)*2 + ((tid&1) ^ ((tid>>3)&1)));

  auto issue = [&](int s){
    uint32_t st = sb + (uint32_t)(s & (NSTG-1))*STAGE_BYTES;
    cpa16(st + dAB,        gA + s*16);
    cpa16(st + 4096 + dAB, gB + s*16);
  };

  uint32_t aoff[4], boff[2];
  #pragma unroll
  for (int mi = 0; mi < 4; mi++){
    int r = wm*64 + mi*16 + (lane & 15);
    int c = lane >> 4;
    aoff[mi] = 16*(r*2 + (c ^ ((r>>2)&1)));
  }
  #pragma unroll
  for (int nj = 0; nj < 2; nj++){
    int n = wn*32 + nj*16 + (lane & 7) + ((lane>>4)<<3);
    int c = (lane>>3)&1;
    boff[nj] = 4096 + 16*(n*2 + (c ^ ((n>>2)&1)));
  }

  float acc[4][4][4];
  #pragma unroll
  for (int mi = 0; mi < 4; mi++)
    #pragma unroll
    for (int q = 0; q < 4; q++)
      #pragma unroll
      for (int v = 0; v < 4; v++) acc[mi][q][v] = 0.f;

  issue(0); CP_COMMIT();
  issue(1); CP_COMMIT();
  issue(2); CP_COMMIT();

  for (int i = 0; i < nsteps; i++){
    CP_WAIT2();
    __syncthreads();
    if (i+3 < nsteps) issue(i+3);
    CP_COMMIT();
    uint32_t st = sb + (uint32_t)(i & (NSTG-1))*STAGE_BYTES;

    uint32_t ah[4][4], bh[2][4];
    #pragma unroll
    for (int mi = 0; mi < 4; mi++) LDSM4(ah[mi], st + aoff[mi]);
    #pragma unroll
    for (int nj = 0; nj < 2; nj++) LDSM4(bh[nj], st + boff[nj]);
    #pragma unroll
    for (int mi = 0; mi < 4; mi++){
      #pragma unroll
      for (int q = 0; q < 4; q++){
        uint32_t b0 = bh[q>>1][(q&1)*2], b1 = bh[q>>1][(q&1)*2+1];
        MMA16816(acc[mi][q], ah[mi], b0, b1);
      }
    }
  }

  #pragma unroll
  for (int mi = 0; mi < 4; mi++){
    int r0 = row0 + wm*64 + mi*16 + (lane>>2);
    int r1 = r0 + 8;
    if (EPI == 0){
      __half* C = (__half*)Cv;
      #pragma unroll
      for (int q = 0; q < 4; q++){
        int cb = col0 + wn*32 + q*8 + 2*(lane&3);
        float bv0 = __ldg(bias+cb), bv1 = __ldg(bias+cb+1);
        *(__half2*)(C + (size_t)r0*ldc + cb) = __floats2half2_rn(acc[mi][q][0]+bv0, acc[mi][q][1]+bv1);
        *(__half2*)(C + (size_t)r1*ldc + cb) = __floats2half2_rn(acc[mi][q][2]+bv0, acc[mi][q][3]+bv1);
      }
    } else {
      float* C = (float*)Cv;
      #pragma unroll
      for (int g = 0; g < 2; g++){
        int cb = col0 + wn*32 + g*16;
        int cA = cb + 2*(lane&3), cB = cb + 8 + 2*(lane&3);
        float bA0 = __ldg(bias+cA), bA1 = __ldg(bias+cA+1);
        float bB0 = __ldg(bias+cB), bB1 = __ldg(bias+cB+1);
        float v0 = fmaxf(fmaxf(acc[mi][2*g][0]+bA0, acc[mi][2*g][1]+bA1),
                         fmaxf(acc[mi][2*g+1][0]+bB0, acc[mi][2*g+1][1]+bB1));
        float v1 = fmaxf(fmaxf(acc[mi][2*g][2]+bA0, acc[mi][2*g][3]+bA1),
                         fmaxf(acc[mi][2*g+1][2]+bB0, acc[mi][2*g+1][3]+bB1));
        v0 = fmaxf(v0, __shfl_xor_sync(0xffffffffu, v0, 1));
        v0 = fmaxf(v0, __shfl_xor_sync(0xffffffffu, v0, 2));
        v1 = fmaxf(v1, __shfl_xor_sync(0xffffffffu, v1, 1));
        v1 = fmaxf(v1, __shfl_xor_sync(0xffffffffu, v1, 2));
        if ((lane & 3) == 0){
          C[(size_t)r0*ldc + (cb>>4)] = v0;
          C[(size_t)r1*ldc + (cb>>4)] = v1;
        }
      }
    }
  }
}

// ================= r = tanh([hx|enc_s|enc_e] @ WD^T) =================
__global__ void __launch_bounds__(256) r_kernel(const float* __restrict__ WD){
  __shared__ float v[1280];
  int b = blockIdx.x, tid = threadIdx.x;
  v[tid] = g_hx[b*H_+tid];
  for (int i = tid; i < 512; i += 256){
    v[256+i] = g_encs[b*512+i];
    v[768+i] = g_ence[b*512+i];
  }
  __syncthreads();
  const float* w = WD + (size_t)tid*1280;
  float acc = 0.f;
  #pragma unroll 4
  for (int k = 0; k < 1280; k += 4){
    float4 wk = *(const float4*)(w+k);
    acc += wk.x*v[k] + wk.y*v[k+1] + wk.z*v[k+2] + wk.w*v[k+3];
  }
  g_r[b*H_+tid] = tanhf(acc);
}

// ====== c[b,j] = r[b,:] . w1r[j,:]  (half weights, fp32 accumulate) ======
__global__ void __launch_bounds__(256) c_kernel(const __half* __restrict__ w1r){
  __shared__ float rs[256];
  int b = blockIdx.y, j = blockIdx.x*256 + threadIdx.x;
  rs[threadIdx.x] = g_r[b*H_+threadIdx.x];
  __syncthreads();
  const __half* wp = w1r + (size_t)j*256;
  float acc = 0.f;
  #pragma unroll 4
  for (int k = 0; k < 256; k += 8){
    uint4 u = *(const uint4*)(wp + k);
    float2 f0 = __half22float2(*(__half2*)&u.x);
    float2 f1 = __half22float2(*(__half2*)&u.y);
    float2 f2 = __half22float2(*(__half2*)&u.z);
    float2 f3 = __half22float2(*(__half2*)&u.w);
    acc += f0.x*rs[k]   + f0.y*rs[k+1] + f1.x*rs[k+2] + f1.y*rs[k+3]
         + f2.x*rs[k+4] + f2.y*rs[k+5] + f3.x*rs[k+6] + f3.y*rs[k+7];
  }
  g_c[b*HP_+j] = acc;
}

// === m1[i,h] = max_p(A[i,h*16+p] + c[b,h*16+p]), i compacted; fp32 + fp16 ===
__global__ void __launch_bounds__(256) m1_kernel(const __half* __restrict__ A){
  int row = blockIdx.x, h = threadIdx.x;
  if (row >= g_nvalid) return;
  int orig = __ldg(&g_rowmap[row]);
  int b = orig >> 9;
  const __half2* ap = (const __half2*)(A   + (size_t)row*HP_ + h*16);
  const float4*  cp = (const float4*) (g_c + (size_t)b  *HP_ + h*16);
  float m = -3.0e38f;
  #pragma unroll
  for (int q = 0; q < 4; q++){
    float4 c = cp[q];
    __half2 a0 = ap[2*q], a1 = ap[2*q+1];
    m = fmaxf(m, fmaxf(fmaxf(__low2float(a0)+c.x, __high2float(a0)+c.y),
                       fmaxf(__low2float(a1)+c.z, __high2float(a1)+c.w)));
  }
  size_t o = (size_t)row*H_ + h;
  g_m1[o]  = m;
  g_m1h[o] = __float2half_rn(m);
}

// === scores[orig] = max_p([m1|m2].w3[p,:] + b3[p]); rows compacted ===
__global__ void __launch_bounds__(128) score_kernel(const float* __restrict__ w3,
                                                    const float* __restrict__ b3){
  __shared__ float sw[16][512];
  int tid = threadIdx.x;
  for (int i = tid; i < 16*512; i += 128) ((float*)sw)[i] = w3[i];
  __syncthreads();
  int row = blockIdx.x*128 + tid;
  if (row >= g_nvalid) return;
  int orig = __ldg(&g_rowmap[row]);
  const float* m1r = g_m1 + (size_t)row*H_;
  const float* m2r = g_m2 + (size_t)row*H_;
  float acc[16];
  #pragma unroll
  for (int p = 0; p < 16; p++) acc[p] = 0.f;
  #pragma unroll 1
  for (int kc = 0; kc < 16; kc++){
    float x[32];
    const float* src = (kc < 8) ? (m1r + kc*32) : (m2r + (kc-8)*32);
    #pragma unroll
    for (int u = 0; u < 8; u++) *(float4*)(x + u*4) = *(const float4*)(src + u*4);
    int kb = kc*32;
    #pragma unroll
    for (int p = 0; p < 16; p++){
      float a = acc[p];
      #pragma unroll
      for (int j = 0; j < 32; j++) a += x[j]*sw[p][kb+j];
      acc[p] = a;
    }
  }
  float m = -3.0e38f;
  #pragma unroll
  for (int p = 0; p < 16; p++) m = fmaxf(m, acc[p] + __ldg(b3+p));
  g_scores[orig] = m;
}

// ========= masked argmax (first-index) + gather, shfl reduction =========
__global__ void __launch_bounds__(512) argmax_kernel(const int* __restrict__ lens,
    float* __restrict__ alphas, float* __restrict__ idx_out, float* __restrict__ enc)
{
  __shared__ float wv[16];
  __shared__ int   wi[16];
  __shared__ int   s_idx;
  int b = blockIdx.x, t = threadIdx.x;
  int lane = t & 31, warp = t >> 5;
  float s = (t < lens[b]) ? g_scores[b*T_+t] : -1.0e9f;
  alphas[(size_t)b*T_ + t] = s;
  float v = s; int idx = t;
  #pragma unroll
  for (int off = 16; off; off >>= 1){
    float v2 = __shfl_xor_sync(0xffffffffu, v, off);
    int   i2 = __shfl_xor_sync(0xffffffffu, idx, off);
    if (v2 > v || (v2 == v && i2 < idx)){ v = v2; idx = i2; }
  }
  if (lane == 0){ wv[warp] = v; wi[warp] = idx; }
  __syncthreads();
  if (warp == 0){
    v = (lane < 16) ? wv[lane] : -3.0e38f;
    idx = (lane < 16) ? wi[lane] : 0x7fffffff;
    #pragma unroll
    for (int off = 16; off; off >>= 1){
      float v2 = __shfl_xor_sync(0xffffffffu, v, off);
      int   i2 = __shfl_xor_sync(0xffffffffu, idx, off);
      if (v2 > v || (v2 == v && i2 < idx)){ v = v2; idx = i2; }
    }
    if (lane == 0){ s_idx = idx; idx_out[b] = (float)idx; }
  }
  __syncthreads();
  int gi = s_idx;
  enc[b*512 + t] = g_Ett[((size_t)b*T_ + gi)*512 + t];
}

// ================= LSTM cell + MLP =================
__global__ void __launch_bounds__(1024) lstm_kernel(
  const float* __restrict__ Wih, const float* __restrict__ Whh,
  const float* __restrict__ bih, const float* __restrict__ bhh,
  const float* __restrict__ Wmlp, const float* __restrict__ bmlp)
{
  __shared__ float xs[1024];
  __shared__ float hs[256];
  __shared__ float gsh[1024];
  __shared__ float hp[256];
  int b = blockIdx.x, tid = threadIdx.x;
  if (tid < 512) xs[tid] = g_encs[b*512+tid];
  else           xs[tid] = g_ence[b*512+tid-512];
  if (tid < 256) hs[tid] = g_hx[b*256+tid];
  __syncthreads();
  {
    const float* wi = Wih + (size_t)tid*1024;
    float acc = bih[tid] + bhh[tid];
    #pragma unroll 4
    for (int k = 0; k < 1024; k += 4){
      float4 w = *(const float4*)(wi+k);
      acc += w.x*xs[k] + w.y*xs[k+1] + w.z*xs[k+2] + w.w*xs[k+3];
    }
    const float* wh = Whh + (size_t)tid*256;
    #pragma unroll 4
    for (int k = 0; k < 256; k += 4){
      float4 w = *(const float4*)(wh+k);
      acc += w.x*hs[k] + w.y*hs[k+1] + w.z*hs[k+2] + w.w*hs[k+3];
    }
    gsh[tid] = acc;
  }
  __syncthreads();
  if (tid < 256){
    float i_ = 1.f/(1.f+expf(-gsh[tid]));
    float f_ = 1.f/(1.f+expf(-gsh[256+tid]));
    float gg = tanhf(gsh[512+tid]);
    float o_ = 1.f/(1.f+expf(-gsh[768+tid]));
    float c  = f_*g_cx[b*256+tid] + i_*gg;
    g_cx[b*256+tid] = c;
    hp[tid] = o_*tanhf(c);
  }
  __syncthreads();
  if (tid < 256){
    const float* wm = Wmlp + (size_t)tid*256;
    float acc = bmlp[tid];
    #pragma unroll 4
    for (int k = 0; k < 256; k += 4){
      float4 w = *(const float4*)(wm+k);
      acc += w.x*hp[k] + w.y*hp[k+1] + w.z*hp[k+2] + w.w*hp[k+3];
    }
    g_hx[b*256+tid] = acc;
  }
}

// ================= host orchestration =================
extern "C" void kernel_launch(void* const* d_in, const int* in_sizes, int n_in,
                              void* d_out, int out_size)
{
  (void)in_sizes; (void)n_in; (void)out_size;
  const float* enc =(const float*)d_in[0];
  const int*   lens=(const int*)  d_in[1];
  const float* WDs =(const float*)d_in[2];
  const float* w1s =(const float*)d_in[3];  const float* b1s=(const float*)d_in[4];
  const float* w2s =(const float*)d_in[5];  const float* b2s=(const float*)d_in[6];
  const float* w3s =(const float*)d_in[7];  const float* b3s=(const float*)d_in[8];
  const float* WDe =(const float*)d_in[9];
  const float* w1e =(const float*)d_in[10]; const float* b1e=(const float*)d_in[11];
  const float* w2e =(const float*)d_in[12]; const float* b2e=(const float*)d_in[13];
  const float* w3e =(const float*)d_in[14]; const float* b3e=(const float*)d_in[15];
  const float* Wih =(const float*)d_in[16]; const float* Whh=(const float*)d_in[17];
  const float* bih =(const float*)d_in[18]; const float* bhh=(const float*)d_in[19];
  const float* Wmlp=(const float*)d_in[20]; const float* bmlp=(const float*)d_in[21];

  float* out = (float*)d_out;
  float* out_start  = out;
  float* out_end    = out + 32;
  float* out_alphas = out + 64;
  float* out_betas  = out + 64 + (size_t)ITERS_*B_*T_;

  float *pm2,*pencs,*pence;
  cudaGetSymbolAddress((void**)&pm2,  g_m2);
  cudaGetSymbolAddress((void**)&pencs,g_encs);
  cudaGetSymbolAddress((void**)&pence,g_ence);

  __half *pEtth,*pAs,*pAe,*pw1sh,*pw1eh,*pw1srh,*pw1erh,*pw2sh,*pw2eh,*pm1h;
  cudaGetSymbolAddress((void**)&pEtth, g_Etth);
  cudaGetSymbolAddress((void**)&pAs,   g_Ah_s);
  cudaGetSymbolAddress((void**)&pAe,   g_Ah_e);
  cudaGetSymbolAddress((void**)&pw1sh, g_w1sh);
  cudaGetSymbolAddress((void**)&pw1eh, g_w1eh);
  cudaGetSymbolAddress((void**)&pw1srh,g_w1srh);
  cudaGetSymbolAddress((void**)&pw1erh,g_w1erh);
  cudaGetSymbolAddress((void**)&pw2sh, g_w2sh);
  cudaGetSymbolAddress((void**)&pw2eh, g_w2eh);
  cudaGetSymbolAddress((void**)&pm1h,  g_m1h);

  cudaFuncSetAttribute(hgemm128<0,1>, cudaFuncAttributeMaxDynamicSharedMemorySize, GEMM_SMEM);
  cudaFuncSetAttribute(hgemm128<1,0>, cudaFuncAttributeMaxDynamicSharedMemorySize, GEMM_SMEM);

  dim3 gG(HP_/128, M_/128);   // (32, 128)

  // Launch order: our 4th launch = hgemm128<0,1> (G1) — the ncu capture slot.
  transpose_kernel<<<dim3(16,16,32), dim3(32,8)>>>(enc);                 // 1
  cvt_kernel<<<(HP_*512+255)/256,256>>>(w1s, 768, 512, pw1sh, HP_*512); // 2
  rowmap_kernel<<<32,512>>>(lens);                                      // 3
  hgemm128<0,1><<<gG,256,GEMM_SMEM>>>(pAs, HP_, pEtth, pw1sh, b1s, 512); // 4 <- ncu
  cvt_kernel<<<(HP_*512+255)/256,256>>>(w1e, 768, 512, pw1eh, HP_*512); // 5
  hgemm128<0,1><<<gG,256,GEMM_SMEM>>>(pAe, HP_, pEtth, pw1eh, b1e, 512); // 6
  init_kernel<<<32,512>>>();                                            // 7

  cvt_kernel<<<(HP_*256+255)/256,256>>>(w1s+512, 768, 256, pw1srh, HP_*256);
  cvt_kernel<<<(HP_*256+255)/256,256>>>(w1e+512, 768, 256, pw1erh, HP_*256);
  cvt_kernel<<<(HP_*256+255)/256,256>>>(w2s, 256, 256, pw2sh, HP_*256);
  cvt_kernel<<<(HP_*256+255)/256,256>>>(w2e, 256, 256, pw2eh, HP_*256);

  for (int it = 0; it < ITERS_; ++it){
    // ---- start net ----
    r_kernel<<<32,256>>>(WDs);
    c_kernel<<<dim3(16,32),256>>>(pw1srh);
    m1_kernel<<<M_,256>>>(pAs);
    hgemm128<1,0><<<gG,256,GEMM_SMEM>>>(pm2, 256, pm1h, pw2sh, b2s, 256);
    score_kernel<<<M_/128,128>>>(w3s, b3s);
    argmax_kernel<<<32,512>>>(lens, out_alphas + (size_t)it*B_*T_, out_start, pencs);
    // ---- end net ----
    r_kernel<<<32,256>>>(WDe);
    c_kernel<<<dim3(16,32),256>>>(pw1erh);
    m1_kernel<<<M_,256>>>(pAe);
    hgemm128<1,0><<<gG,256,GEMM_SMEM>>>(pm2, 256, pm1h, pw2eh, b2e, 256);
    score_kernel<<<M_/128,128>>>(w3e, b3e);
    argmax_kernel<<<32,512>>>(lens, out_betas + (size_t)it*B_*T_, out_end, pence);
    // ---- LSTM + MLP ----
    lstm_kernel<<<32,1024>>>(Wih, Whh, bih, bhh, Wmlp, bmlp);
  }
}

// round 16
// speedup vs baseline: 3.9199x; 1.0300x over previous
#include <cuda_runtime.h>
#include <cuda_fp16.h>
#include <math.h>
#include <stdint.h>

// Problem constants
#define B_   32
#define T_   512
#define H_   256
#define P_   16
#define M_   (B_*T_)     // 16384 rows
#define HP_  4096        // H*P
#define ITERS_ 4

// ================= device scratch (static, no allocation) =================
__device__ float g_Ett [(size_t)M_*512];
__device__ float g_m1  [(size_t)M_*H_];
__device__ float g_m2  [(size_t)M_*H_];
__device__ float g_scores[M_];
__device__ float g_c   [B_*HP_];
__device__ float g_r   [B_*H_];
__device__ float g_encs[B_*512];
__device__ float g_ence[B_*512];
__device__ float g_hx  [B_*H_];
__device__ float g_cx  [B_*H_];

// row compaction (valid rows first; entries >= nvalid stay 0 = safe row)
__device__ int g_rowmap[M_];
__device__ int g_nvalid;

// fp16 operands
__device__ __half g_Etth [(size_t)M_*512];
__device__ __half g_Ah_s [(size_t)M_*HP_];   // A = Et@w1s[:, :512]^T + b1s (half, COMPACTED rows)
__device__ __half g_Ah_e [(size_t)M_*HP_];
__device__ __half g_w1sh [(size_t)HP_*512];
__device__ __half g_w1eh [(size_t)HP_*512];
__device__ __half g_w1srh[(size_t)HP_*256];  // w1[:, 512:768]
__device__ __half g_w1erh[(size_t)HP_*256];
__device__ __half g_w2sh [(size_t)HP_*256];
__device__ __half g_w2eh [(size_t)HP_*256];
__device__ __half g_m1h  [(size_t)M_*256];   // compacted rows

// ================= helpers =================
__device__ __forceinline__ uint32_t smem_u32(const void* p){
  uint32_t a;
  asm("{ .reg .u64 t; cvta.to.shared.u64 t, %1; cvt.u32.u64 %0, t; }" : "=r"(a) : "l"(p));
  return a;
}
__device__ __forceinline__ void cpa16(uint32_t dst, const void* src){
  asm volatile("cp.async.cg.shared.global [%0], [%1], 16;" :: "r"(dst), "l"(src));
}
#define CP_COMMIT() asm volatile("cp.async.commit_group;" ::: "memory")
#define CP_WAIT2()  asm volatile("cp.async.wait_group 2;"  ::: "memory")

#define LDSM4(r, a) \
  asm volatile("ldmatrix.sync.aligned.m8n8.x4.shared.b16 {%0,%1,%2,%3}, [%4];" \
    : "=r"((r)[0]),"=r"((r)[1]),"=r"((r)[2]),"=r"((r)[3]) : "r"(a))

#define MMA16816(d, a, b0, b1) \
  asm volatile("mma.sync.aligned.m16n8k16.row.col.f32.f16.f16.f32 " \
    "{%0,%1,%2,%3}, {%4,%5,%6,%7}, {%8,%9}, {%0,%1,%2,%3};" \
    : "+f"((d)[0]),"+f"((d)[1]),"+f"((d)[2]),"+f"((d)[3]) \
    : "r"((a)[0]),"r"((a)[1]),"r"((a)[2]),"r"((a)[3]), "r"(b0),"r"(b1))

// ========= transpose: enc[B,2H,T] -> Ett[B*T, 2H] (fp32 + fp16) =========
__global__ void transpose_kernel(const float* __restrict__ enc){
  __shared__ float tile[32][33];
  int b  = blockIdx.z;
  int t0 = blockIdx.x*32, c0 = blockIdx.y*32;
  int x  = threadIdx.x;
  for (int i = threadIdx.y; i < 32; i += 8)
    tile[i][x] = enc[((size_t)b*512 + (c0+i))*512 + t0 + x];
  __syncthreads();
  for (int i = threadIdx.y; i < 32; i += 8){
    float v = tile[x][i];
    size_t o = ((size_t)b*512 + (t0+i))*512 + c0 + x;
    g_Ett[o]  = v;
    g_Etth[o] = __float2half_rn(v);
  }
}

__global__ void init_kernel(){
  int b = blockIdx.x, t = threadIdx.x;
  float v = g_Ett[((size_t)b*512)*512 + t];
  g_encs[b*512+t] = v;
  g_ence[b*512+t] = v;
  if (t < H_){ g_hx[b*H_+t] = 0.f; g_cx[b*H_+t] = 0.f; }
}

// ========= rowmap: compact valid rows (t < len[b]) to the front =========
__global__ void rowmap_kernel(const int* __restrict__ lens){
  __shared__ int start;
  int b = blockIdx.x, t = threadIdx.x;   // 32 blocks x 512
  if (t == 0){
    int s = 0;
    for (int i = 0; i < b; i++) s += lens[i];
    start = s;
    if (b == 0){
      int tot = 0;
      for (int i = 0; i < B_; i++) tot += lens[i];
      g_nvalid = tot;
    }
  }
  __syncthreads();
  if (t < lens[b]) g_rowmap[start + t] = b*512 + t;
}

// ================= fp32 (strided) -> fp16 =================
__global__ void __launch_bounds__(256) cvt_kernel(const float* __restrict__ src, int ld, int cols,
                                                  __half* __restrict__ dst, int total)
{
  int idx = blockIdx.x*256 + threadIdx.x;
  if (idx >= total) return;
  int r = idx / cols, c = idx - r*cols;
  dst[idx] = __float2half_rn(src[(size_t)r*ld + c]);
}

// ===== Unified HMMA GEMM (fp32 acc): 128x128 tile, COMPACTED rows =====
// 8 warps (2x4), warp tile 64x32. K=32 stages (2 x k16 sub-steps per barrier),
// 4-stage cp.async. Stage layout: A0 | A1 | B0 | B1, 4KB each (proven sub-tile layout).
// MAP=1: A rows gathered through g_rowmap (G1). MAP=0: A compacted-dense (G2).
// EPI=0: bias + fp16 store (C half*, ldc).  EPI=1: bias + maxout/16 (C float*, ldc).
#define STAGE32 16384
#define NSTG 4
#define GEMM_SMEM (NSTG*STAGE32)   // 64KB

template<int EPI, int MAP>
__global__ void __launch_bounds__(256, 2)
hgemm128(void* __restrict__ Cv, int ldc,
         const __half* __restrict__ A, const __half* __restrict__ B,
         const float* __restrict__ bias, int K)
{
  const int row0 = blockIdx.y*128, col0 = blockIdx.x*128;
  if (row0 >= g_nvalid) return;   // tile fully beyond compacted valid rows

  extern __shared__ char smem[];
  uint32_t sb = smem_u32(smem);
  const int tid = threadIdx.x, lane = tid & 31, warp = tid >> 5;
  const int wm = warp >> 2, wn = warp & 3;
  const int nstg = K >> 5;       // K32 stages

  int ar = row0 + (tid>>1);
  if (MAP) ar = __ldg(&g_rowmap[ar]);   // entries >= nvalid are 0 -> safe
  const __half* gA = A + (size_t)ar*K + (tid&1)*8;
  const __half* gB = B + (size_t)(col0 + (tid>>1))*K + (tid&1)*8;
  const uint32_t dAB = 16*((tid>>1)*2 + ((tid&1) ^ ((tid>>3)&1)));

  auto issue = [&](int s){
    uint32_t st = sb + (uint32_t)(s & (NSTG-1))*STAGE32;
    const __half* a0 = gA + s*32;
    const __half* b0 = gB + s*32;
    cpa16(st         + dAB, a0);
    cpa16(st +  4096 + dAB, a0 + 16);
    cpa16(st +  8192 + dAB, b0);
    cpa16(st + 12288 + dAB, b0 + 16);
  };

  uint32_t aoff[4], boff[2];    // sub-tile-relative (4KB tiles, proven layout)
  #pragma unroll
  for (int mi = 0; mi < 4; mi++){
    int r = wm*64 + mi*16 + (lane & 15);
    int c = lane >> 4;
    aoff[mi] = 16*(r*2 + (c ^ ((r>>2)&1)));
  }
  #pragma unroll
  for (int nj = 0; nj < 2; nj++){
    int n = wn*32 + nj*16 + (lane & 7) + ((lane>>4)<<3);
    int c = (lane>>3)&1;
    boff[nj] = 16*(n*2 + (c ^ ((n>>2)&1)));
  }

  float acc[4][4][4];
  #pragma unroll
  for (int mi = 0; mi < 4; mi++)
    #pragma unroll
    for (int q = 0; q < 4; q++)
      #pragma unroll
      for (int v = 0; v < 4; v++) acc[mi][q][v] = 0.f;

  issue(0); CP_COMMIT();
  issue(1); CP_COMMIT();
  issue(2); CP_COMMIT();

  for (int i = 0; i < nstg; i++){
    CP_WAIT2();
    __syncthreads();
    if (i+3 < nstg) issue(i+3);
    CP_COMMIT();
    uint32_t st = sb + (uint32_t)(i & (NSTG-1))*STAGE32;

    #pragma unroll
    for (int sub = 0; sub < 2; sub++){
      uint32_t ab = st + (uint32_t)sub*4096;
      uint32_t bb = st + 8192 + (uint32_t)sub*4096;
      uint32_t ah[4][4], bh[2][4];
      #pragma unroll
      for (int mi = 0; mi < 4; mi++) LDSM4(ah[mi], ab + aoff[mi]);
      #pragma unroll
      for (int nj = 0; nj < 2; nj++) LDSM4(bh[nj], bb + boff[nj]);
      #pragma unroll
      for (int mi = 0; mi < 4; mi++){
        #pragma unroll
        for (int q = 0; q < 4; q++){
          uint32_t b0 = bh[q>>1][(q&1)*2], b1 = bh[q>>1][(q&1)*2+1];
          MMA16816(acc[mi][q], ah[mi], b0, b1);
        }
      }
    }
  }

  #pragma unroll
  for (int mi = 0; mi < 4; mi++){
    int r0 = row0 + wm*64 + mi*16 + (lane>>2);
    int r1 = r0 + 8;
    if (EPI == 0){
      __half* C = (__half*)Cv;
      #pragma unroll
      for (int q = 0; q < 4; q++){
        int cb = col0 + wn*32 + q*8 + 2*(lane&3);
        float bv0 = __ldg(bias+cb), bv1 = __ldg(bias+cb+1);
        *(__half2*)(C + (size_t)r0*ldc + cb) = __floats2half2_rn(acc[mi][q][0]+bv0, acc[mi][q][1]+bv1);
        *(__half2*)(C + (size_t)r1*ldc + cb) = __floats2half2_rn(acc[mi][q][2]+bv0, acc[mi][q][3]+bv1);
      }
    } else {
      float* C = (float*)Cv;
      #pragma unroll
      for (int g = 0; g < 2; g++){
        int cb = col0 + wn*32 + g*16;
        int cA = cb + 2*(lane&3), cB = cb + 8 + 2*(lane&3);
        float bA0 = __ldg(bias+cA), bA1 = __ldg(bias+cA+1);
        float bB0 = __ldg(bias+cB), bB1 = __ldg(bias+cB+1);
        float v0 = fmaxf(fmaxf(acc[mi][2*g][0]+bA0, acc[mi][2*g][1]+bA1),
                         fmaxf(acc[mi][2*g+1][0]+bB0, acc[mi][2*g+1][1]+bB1));
        float v1 = fmaxf(fmaxf(acc[mi][2*g][2]+bA0, acc[mi][2*g][3]+bA1),
                         fmaxf(acc[mi][2*g+1][2]+bB0, acc[mi][2*g+1][3]+bB1));
        v0 = fmaxf(v0, __shfl_xor_sync(0xffffffffu, v0, 1));
        v0 = fmaxf(v0, __shfl_xor_sync(0xffffffffu, v0, 2));
        v1 = fmaxf(v1, __shfl_xor_sync(0xffffffffu, v1, 1));
        v1 = fmaxf(v1, __shfl_xor_sync(0xffffffffu, v1, 2));
        if ((lane & 3) == 0){
          C[(size_t)r0*ldc + (cb>>4)] = v0;
          C[(size_t)r1*ldc + (cb>>4)] = v1;
        }
      }
    }
  }
}

// ================= r = tanh([hx|enc_s|enc_e] @ WD^T) =================
__global__ void __launch_bounds__(256) r_kernel(const float* __restrict__ WD){
  __shared__ float v[1280];
  int b = blockIdx.x, tid = threadIdx.x;
  v[tid] = g_hx[b*H_+tid];
  for (int i = tid; i < 512; i += 256){
    v[256+i] = g_encs[b*512+i];
    v[768+i] = g_ence[b*512+i];
  }
  __syncthreads();
  const float* w = WD + (size_t)tid*1280;
  float acc = 0.f;
  #pragma unroll 4
  for (int k = 0; k < 1280; k += 4){
    float4 wk = *(const float4*)(w+k);
    acc += wk.x*v[k] + wk.y*v[k+1] + wk.z*v[k+2] + wk.w*v[k+3];
  }
  g_r[b*H_+tid] = tanhf(acc);
}

// ====== c[b,j] = r[b,:] . w1r[j,:]  (half weights, fp32 accumulate) ======
__global__ void __launch_bounds__(256) c_kernel(const __half* __restrict__ w1r){
  __shared__ float rs[256];
  int b = blockIdx.y, j = blockIdx.x*256 + threadIdx.x;
  rs[threadIdx.x] = g_r[b*H_+threadIdx.x];
  __syncthreads();
  const __half* wp = w1r + (size_t)j*256;
  float acc = 0.f;
  #pragma unroll 4
  for (int k = 0; k < 256; k += 8){
    uint4 u = *(const uint4*)(wp + k);
    float2 f0 = __half22float2(*(__half2*)&u.x);
    float2 f1 = __half22float2(*(__half2*)&u.y);
    float2 f2 = __half22float2(*(__half2*)&u.z);
    float2 f3 = __half22float2(*(__half2*)&u.w);
    acc += f0.x*rs[k]   + f0.y*rs[k+1] + f1.x*rs[k+2] + f1.y*rs[k+3]
         + f2.x*rs[k+4] + f2.y*rs[k+5] + f3.x*rs[k+6] + f3.y*rs[k+7];
  }
  g_c[b*HP_+j] = acc;
}

// === m1[i,h] = max_p(A[i,h*16+p] + c[b,h*16+p]), i compacted; fp32 + fp16 ===
__global__ void __launch_bounds__(256) m1_kernel(const __half* __restrict__ A){
  int row = blockIdx.x, h = threadIdx.x;
  if (row >= g_nvalid) return;
  int orig = __ldg(&g_rowmap[row]);
  int b = orig >> 9;
  const uint4*  ap4 = (const uint4*) (A   + (size_t)row*HP_ + h*16);
  const float4* cp  = (const float4*)(g_c + (size_t)b  *HP_ + h*16);
  uint4 av0 = ap4[0], av1 = ap4[1];
  const uint32_t* a2a = (const uint32_t*)&av0;
  const uint32_t* a2b = (const uint32_t*)&av1;
  float m = -3.0e38f;
  #pragma unroll
  for (int q = 0; q < 2; q++){
    float4 c = cp[q];
    float2 fa = __half22float2(*(const __half2*)&a2a[2*q]);
    float2 fb = __half22float2(*(const __half2*)&a2a[2*q+1]);
    m = fmaxf(m, fmaxf(fmaxf(fa.x+c.x, fa.y+c.y), fmaxf(fb.x+c.z, fb.y+c.w)));
  }
  #pragma unroll
  for (int q = 0; q < 2; q++){
    float4 c = cp[2+q];
    float2 fa = __half22float2(*(const __half2*)&a2b[2*q]);
    float2 fb = __half22float2(*(const __half2*)&a2b[2*q+1]);
    m = fmaxf(m, fmaxf(fmaxf(fa.x+c.x, fa.y+c.y), fmaxf(fb.x+c.z, fb.y+c.w)));
  }
  size_t o = (size_t)row*H_ + h;
  g_m1[o]  = m;
  g_m1h[o] = __float2half_rn(m);
}

// === scores[orig] = max_p([m1|m2].w3[p,:] + b3[p]); rows compacted ===
__global__ void __launch_bounds__(128) score_kernel(const float* __restrict__ w3,
                                                    const float* __restrict__ b3){
  __shared__ float sw[16][512];
  int tid = threadIdx.x;
  for (int i = tid; i < 16*512; i += 128) ((float*)sw)[i] = w3[i];
  __syncthreads();
  int row = blockIdx.x*128 + tid;
  if (row >= g_nvalid) return;
  int orig = __ldg(&g_rowmap[row]);
  const float* m1r = g_m1 + (size_t)row*H_;
  const float* m2r = g_m2 + (size_t)row*H_;
  float acc[16];
  #pragma unroll
  for (int p = 0; p < 16; p++) acc[p] = 0.f;
  #pragma unroll 1
  for (int kc = 0; kc < 16; kc++){
    float x[32];
    const float* src = (kc < 8) ? (m1r + kc*32) : (m2r + (kc-8)*32);
    #pragma unroll
    for (int u = 0; u < 8; u++) *(float4*)(x + u*4) = *(const float4*)(src + u*4);
    int kb = kc*32;
    #pragma unroll
    for (int p = 0; p < 16; p++){
      float a = acc[p];
      #pragma unroll
      for (int j = 0; j < 32; j++) a += x[j]*sw[p][kb+j];
      acc[p] = a;
    }
  }
  float m = -3.0e38f;
  #pragma unroll
  for (int p = 0; p < 16; p++) m = fmaxf(m, acc[p] + __ldg(b3+p));
  g_scores[orig] = m;
}

// ========= masked argmax (first-index) + gather, shfl reduction =========
__global__ void __launch_bounds__(512) argmax_kernel(const int* __restrict__ lens,
    float* __restrict__ alphas, float* __restrict__ idx_out, float* __restrict__ enc)
{
  __shared__ float wv[16];
  __shared__ int   wi[16];
  __shared__ int   s_idx;
  int b = blockIdx.x, t = threadIdx.x;
  int lane = t & 31, warp = t >> 5;
  float s = (t < lens[b]) ? g_scores[b*T_+t] : -1.0e9f;
  alphas[(size_t)b*T_ + t] = s;
  float v = s; int idx = t;
  #pragma unroll
  for (int off = 16; off; off >>= 1){
    float v2 = __shfl_xor_sync(0xffffffffu, v, off);
    int   i2 = __shfl_xor_sync(0xffffffffu, idx, off);
    if (v2 > v || (v2 == v && i2 < idx)){ v = v2; idx = i2; }
  }
  if (lane == 0){ wv[warp] = v; wi[warp] = idx; }
  __syncthreads();
  if (warp == 0){
    v = (lane < 16) ? wv[lane] : -3.0e38f;
    idx = (lane < 16) ? wi[lane] : 0x7fffffff;
    #pragma unroll
    for (int off = 16; off; off >>= 1){
      float v2 = __shfl_xor_sync(0xffffffffu, v, off);
      int   i2 = __shfl_xor_sync(0xffffffffu, idx, off);
      if (v2 > v || (v2 == v && i2 < idx)){ v = v2; idx = i2; }
    }
    if (lane == 0){ s_idx = idx; idx_out[b] = (float)idx; }
  }
  __syncthreads();
  int gi = s_idx;
  enc[b*512 + t] = g_Ett[((size_t)b*T_ + gi)*512 + t];
}

// ================= LSTM cell + MLP =================
__global__ void __launch_bounds__(1024) lstm_kernel(
  const float* __restrict__ Wih, const float* __restrict__ Whh,
  const float* __restrict__ bih, const float* __restrict__ bhh,
  const float* __restrict__ Wmlp, const float* __restrict__ bmlp)
{
  __shared__ float xs[1024];
  __shared__ float hs[256];
  __shared__ float gsh[1024];
  __shared__ float hp[256];
  int b = blockIdx.x, tid = threadIdx.x;
  if (tid < 512) xs[tid] = g_encs[b*512+tid];
  else           xs[tid] = g_ence[b*512+tid-512];
  if (tid < 256) hs[tid] = g_hx[b*256+tid];
  __syncthreads();
  {
    const float* wi = Wih + (size_t)tid*1024;
    float acc = bih[tid] + bhh[tid];
    #pragma unroll 4
    for (int k = 0; k < 1024; k += 4){
      float4 w = *(const float4*)(wi+k);
      acc += w.x*xs[k] + w.y*xs[k+1] + w.z*xs[k+2] + w.w*xs[k+3];
    }
    const float* wh = Whh + (size_t)tid*256;
    #pragma unroll 4
    for (int k = 0; k < 256; k += 4){
      float4 w = *(const float4*)(wh+k);
      acc += w.x*hs[k] + w.y*hs[k+1] + w.z*hs[k+2] + w.w*hs[k+3];
    }
    gsh[tid] = acc;
  }
  __syncthreads();
  if (tid < 256){
    float i_ = 1.f/(1.f+expf(-gsh[tid]));
    float f_ = 1.f/(1.f+expf(-gsh[256+tid]));
    float gg = tanhf(gsh[512+tid]);
    float o_ = 1.f/(1.f+expf(-gsh[768+tid]));
    float c  = f_*g_cx[b*256+tid] + i_*gg;
    g_cx[b*256+tid] = c;
    hp[tid] = o_*tanhf(c);
  }
  __syncthreads();
  if (tid < 256){
    const float* wm = Wmlp + (size_t)tid*256;
    float acc = bmlp[tid];
    #pragma unroll 4
    for (int k = 0; k < 256; k += 4){
      float4 w = *(const float4*)(wm+k);
      acc += w.x*hp[k] + w.y*hp[k+1] + w.z*hp[k+2] + w.w*hp[k+3];
    }
    g_hx[b*256+tid] = acc;
  }
}

// ================= host orchestration =================
extern "C" void kernel_launch(void* const* d_in, const int* in_sizes, int n_in,
                              void* d_out, int out_size)
{
  (void)in_sizes; (void)n_in; (void)out_size;
  const float* enc =(const float*)d_in[0];
  const int*   lens=(const int*)  d_in[1];
  const float* WDs =(const float*)d_in[2];
  const float* w1s =(const float*)d_in[3];  const float* b1s=(const float*)d_in[4];
  const float* w2s =(const float*)d_in[5];  const float* b2s=(const float*)d_in[6];
  const float* w3s =(const float*)d_in[7];  const float* b3s=(const float*)d_in[8];
  const float* WDe =(const float*)d_in[9];
  const float* w1e =(const float*)d_in[10]; const float* b1e=(const float*)d_in[11];
  const float* w2e =(const float*)d_in[12]; const float* b2e=(const float*)d_in[13];
  const float* w3e =(const float*)d_in[14]; const float* b3e=(const float*)d_in[15];
  const float* Wih =(const float*)d_in[16]; const float* Whh=(const float*)d_in[17];
  const float* bih =(const float*)d_in[18]; const float* bhh=(const float*)d_in[19];
  const float* Wmlp=(const float*)d_in[20]; const float* bmlp=(const float*)d_in[21];

  float* out = (float*)d_out;
  float* out_start  = out;
  float* out_end    = out + 32;
  float* out_alphas = out + 64;
  float* out_betas  = out + 64 + (size_t)ITERS_*B_*T_;

  float *pm2,*pencs,*pence;
  cudaGetSymbolAddress((void**)&pm2,  g_m2);
  cudaGetSymbolAddress((void**)&pencs,g_encs);
  cudaGetSymbolAddress((void**)&pence,g_ence);

  __half *pEtth,*pAs,*pAe,*pw1sh,*pw1eh,*pw1srh,*pw1erh,*pw2sh,*pw2eh,*pm1h;
  cudaGetSymbolAddress((void**)&pEtth, g_Etth);
  cudaGetSymbolAddress((void**)&pAs,   g_Ah_s);
  cudaGetSymbolAddress((void**)&pAe,   g_Ah_e);
  cudaGetSymbolAddress((void**)&pw1sh, g_w1sh);
  cudaGetSymbolAddress((void**)&pw1eh, g_w1eh);
  cudaGetSymbolAddress((void**)&pw1srh,g_w1srh);
  cudaGetSymbolAddress((void**)&pw1erh,g_w1erh);
  cudaGetSymbolAddress((void**)&pw2sh, g_w2sh);
  cudaGetSymbolAddress((void**)&pw2eh, g_w2eh);
  cudaGetSymbolAddress((void**)&pm1h,  g_m1h);

  cudaFuncSetAttribute(hgemm128<0,1>, cudaFuncAttributeMaxDynamicSharedMemorySize, GEMM_SMEM);
  cudaFuncSetAttribute(hgemm128<1,0>, cudaFuncAttributeMaxDynamicSharedMemorySize, GEMM_SMEM);

  dim3 gG(HP_/128, M_/128);   // (32, 128)

  // Launch order: our 4th launch = hgemm128<0,1> (G1) — the ncu capture slot.
  transpose_kernel<<<dim3(16,16,32), dim3(32,8)>>>(enc);                 // 1
  cvt_kernel<<<(HP_*512+255)/256,256>>>(w1s, 768, 512, pw1sh, HP_*512); // 2
  rowmap_kernel<<<32,512>>>(lens);                                      // 3
  hgemm128<0,1><<<gG,256,GEMM_SMEM>>>(pAs, HP_, pEtth, pw1sh, b1s, 512); // 4 <- ncu
  cvt_kernel<<<(HP_*512+255)/256,256>>>(w1e, 768, 512, pw1eh, HP_*512); // 5
  hgemm128<0,1><<<gG,256,GEMM_SMEM>>>(pAe, HP_, pEtth, pw1eh, b1e, 512); // 6
  init_kernel<<<32,512>>>();                                            // 7

  cvt_kernel<<<(HP_*256+255)/256,256>>>(w1s+512, 768, 256, pw1srh, HP_*256);
  cvt_kernel<<<(HP_*256+255)/256,256>>>(w1e+512, 768, 256, pw1erh, HP_*256);
  cvt_kernel<<<(HP_*256+255)/256,256>>>(w2s, 256, 256, pw2sh, HP_*256);
  cvt_kernel<<<(HP_*256+255)/256,256>>>(w2e, 256, 256, pw2eh, HP_*256);

  for (int it = 0; it < ITERS_; ++it){
    // ---- start net ----
    r_kernel<<<32,256>>>(WDs);
    c_kernel<<<dim3(16,32),256>>>(pw1srh);
    m1_kernel<<<M_,256>>>(pAs);
    hgemm128<1,0><<<gG,256,GEMM_SMEM>>>(pm2, 256, pm1h, pw2sh, b2s, 256);
    score_kernel<<<M_/128,128>>>(w3s, b3s);
    argmax_kernel<<<32,512>>>(lens, out_alphas + (size_t)it*B_*T_, out_start, pencs);
    // ---- end net ----
    r_kernel<<<32,256>>>(WDe);
    c_kernel<<<dim3(16,32),256>>>(pw1erh);
    m1_kernel<<<M_,256>>>(pAe);
    hgemm128<1,0><<<gG,256,GEMM_SMEM>>>(pm2, 256, pm1h, pw2eh, b2e, 256);
    score_kernel<<<M_/128,128>>>(w3e, b3e);
    argmax_kernel<<<32,512>>>(lens, out_betas + (size_t)it*B_*T_, out_end, pence);
    // ---- LSTM + MLP ----
    lstm_kernel<<<32,1024>>>(Wih, Whh, bih, bhh, Wmlp, bmlp);
  }
}